// round 1
// baseline (speedup 1.0000x reference)
#include <cuda_runtime.h>
#include <cstdint>
#include <math.h>

// Problem constants
#define B_ 4
#define T_ 2048
#define C_ 1024
#define H_ 16
#define D_ 64
#define BH_ (B_ * H_)

// Scratch (device globals -- no allocation allowed)
__device__ float g_q[BH_ * T_ * D_];   // [B,H,T,D] 32MB
__device__ float g_k[BH_ * T_ * D_];   // 32MB
__device__ float g_v[BH_ * T_ * D_];   // 32MB
__device__ float g_y[B_ * T_ * C_];    // [B,T,H,D] = [B,T,C] 32MB

// ---------------------------------------------------------------------------
// TF32 helpers
// ---------------------------------------------------------------------------
__device__ __forceinline__ float tf32_round(float x) {
    uint32_t u;
    asm("cvt.rna.tf32.f32 %0, %1;" : "=r"(u) : "f"(x));
    return __uint_as_float(u);
}

__device__ __forceinline__ void mma_tf32(float d[4], const uint32_t a[4],
                                         const uint32_t b[2], const float c[4]) {
    asm volatile(
        "mma.sync.aligned.m16n8k8.row.col.f32.tf32.tf32.f32 "
        "{%0,%1,%2,%3},{%4,%5,%6,%7},{%8,%9},{%10,%11,%12,%13};"
        : "=f"(d[0]), "=f"(d[1]), "=f"(d[2]), "=f"(d[3])
        : "r"(a[0]), "r"(a[1]), "r"(a[2]), "r"(a[3]),
          "r"(b[0]), "r"(b[1]),
          "f"(c[0]), "f"(c[1]), "f"(c[2]), "f"(c[3]));
}

// ---------------------------------------------------------------------------
// Generic TF32 GEMM: C[M,N] = A[M,K] @ W[K,N] + bias
// MODE 0: scatter epilogue into g_q/g_k/g_v   (QKV projection)
// MODE 1: plain row-major store into Cout     (output projection)
// Tiles: BM=128 BN=128 BK=16, 256 threads = 8 warps (2x4), warp tile 64x32.
// ---------------------------------------------------------------------------
template <int MODE>
__global__ __launch_bounds__(256) void gemm_tf32_kernel(
    const float* __restrict__ A, const float* __restrict__ W,
    const float* __restrict__ bias, float* __restrict__ Cout,
    int M, int N, int K)
{
    __shared__ float As[128][17];   // padded to kill row-stride conflicts
    __shared__ float Bs[16][132];

    const int tid  = threadIdx.x;
    const int lane = tid & 31;
    const int wid  = tid >> 5;
    const int g    = lane >> 2;     // group id (row within mma tile)
    const int tg   = lane & 3;      // thread-in-group (col quad)
    const int wr   = (wid >> 2) * 64;   // warp row offset in block tile
    const int wc   = (wid & 3) * 32;    // warp col offset in block tile
    const int m0   = blockIdx.y * 128;
    const int n0   = blockIdx.x * 128;

    float acc[4][4][4];
#pragma unroll
    for (int mi = 0; mi < 4; mi++)
#pragma unroll
        for (int ni = 0; ni < 4; ni++)
#pragma unroll
            for (int r = 0; r < 4; r++) acc[mi][ni][r] = 0.0f;

    for (int k0 = 0; k0 < K; k0 += 16) {
        // Load A tile 128x16 (512 float4)
#pragma unroll
        for (int i = 0; i < 2; i++) {
            int idx = tid + i * 256;
            int r = idx >> 2, c4 = (idx & 3) << 2;
            float4 v = *(const float4*)&A[(size_t)(m0 + r) * K + k0 + c4];
            As[r][c4 + 0] = tf32_round(v.x);
            As[r][c4 + 1] = tf32_round(v.y);
            As[r][c4 + 2] = tf32_round(v.z);
            As[r][c4 + 3] = tf32_round(v.w);
        }
        // Load B tile 16x128 (512 float4)
#pragma unroll
        for (int i = 0; i < 2; i++) {
            int idx = tid + i * 256;
            int r = idx >> 5, c4 = (idx & 31) << 2;
            float4 v = *(const float4*)&W[(size_t)(k0 + r) * N + n0 + c4];
            Bs[r][c4 + 0] = tf32_round(v.x);
            Bs[r][c4 + 1] = tf32_round(v.y);
            Bs[r][c4 + 2] = tf32_round(v.z);
            Bs[r][c4 + 3] = tf32_round(v.w);
        }
        __syncthreads();

#pragma unroll
        for (int kk = 0; kk < 2; kk++) {
            uint32_t af[4][4];
            uint32_t bf[4][2];
#pragma unroll
            for (int mi = 0; mi < 4; mi++) {
                int r = wr + mi * 16;
                af[mi][0] = __float_as_uint(As[r + g    ][kk * 8 + tg    ]);
                af[mi][1] = __float_as_uint(As[r + g + 8][kk * 8 + tg    ]);
                af[mi][2] = __float_as_uint(As[r + g    ][kk * 8 + tg + 4]);
                af[mi][3] = __float_as_uint(As[r + g + 8][kk * 8 + tg + 4]);
            }
#pragma unroll
            for (int ni = 0; ni < 4; ni++) {
                int c = wc + ni * 8 + g;
                bf[ni][0] = __float_as_uint(Bs[kk * 8 + tg    ][c]);
                bf[ni][1] = __float_as_uint(Bs[kk * 8 + tg + 4][c]);
            }
#pragma unroll
            for (int mi = 0; mi < 4; mi++)
#pragma unroll
                for (int ni = 0; ni < 4; ni++)
                    mma_tf32(acc[mi][ni], af[mi], bf[ni], acc[mi][ni]);
        }
        __syncthreads();
    }

    // Epilogue
#pragma unroll
    for (int mi = 0; mi < 4; mi++) {
#pragma unroll
        for (int ni = 0; ni < 4; ni++) {
#pragma unroll
            for (int r = 0; r < 4; r++) {
                int row = m0 + wr + mi * 16 + g + ((r >> 1) ? 8 : 0);
                int col = n0 + wc + ni * 8 + tg * 2 + (r & 1);
                float v = acc[mi][ni][r] + bias[col];
                if (MODE == 0) {
                    // qkv scatter: row -> (b,t), col -> (which,h,d)
                    int b = row >> 11;          // /T_
                    int t = row & (T_ - 1);
                    int which = col >> 10;      // /C_
                    int rr = col & (C_ - 1);
                    int h = rr >> 6;
                    int d = rr & 63;
                    float* dst = (which == 0) ? g_q : (which == 1) ? g_k : g_v;
                    dst[(((size_t)(b * H_ + h)) * T_ + t) * D_ + d] = v;
                } else {
                    Cout[(size_t)row * N + col] = v;
                }
            }
        }
    }
}

// ---------------------------------------------------------------------------
// Flash attention (causal), TF32 mma, BQ=64 BKV=64, 128 threads (4 warps),
// each warp owns a 16-row slab of Q. D = 64.
// ---------------------------------------------------------------------------
#define SMS 68                      // smem row stride (floats)
#define ATTN_SMEM (4 * 64 * SMS * 4)  // Q,K,V,P tiles = 69632 bytes

__global__ __launch_bounds__(128) void attn_kernel()
{
    extern __shared__ float sm[];
    float* Qs = sm;
    float* Ks = sm + 64 * SMS;
    float* Vs = sm + 2 * 64 * SMS;
    float* Ps = sm + 3 * 64 * SMS;

    const int bh  = blockIdx.x;           // b*H + h
    const int b   = bh >> 4;
    const int h   = bh & 15;
    const int qi  = blockIdx.y;           // q tile index
    const int tid = threadIdx.x;
    const int lane = tid & 31;
    const int wid  = tid >> 5;
    const int g    = lane >> 2;
    const int tg   = lane & 3;

    const float* Qg = g_q + ((size_t)bh * T_ + qi * 64) * D_;
    const float* Kg = g_k + (size_t)bh * T_ * D_;
    const float* Vg = g_v + (size_t)bh * T_ * D_;

    // Load Q tile (64x64)
    for (int i = tid; i < 1024; i += 128) {
        int r = i >> 4, c = (i & 15) << 2;
        float4 v = *(const float4*)&Qg[r * D_ + c];
        Qs[r * SMS + c + 0] = tf32_round(v.x);
        Qs[r * SMS + c + 1] = tf32_round(v.y);
        Qs[r * SMS + c + 2] = tf32_round(v.z);
        Qs[r * SMS + c + 3] = tf32_round(v.w);
    }

    float O[8][4];
#pragma unroll
    for (int ni = 0; ni < 8; ni++)
#pragma unroll
        for (int r = 0; r < 4; r++) O[ni][r] = 0.0f;
    float mrow0 = -1e30f, mrow1 = -1e30f;
    float lrow0 = 0.0f,   lrow1 = 0.0f;

    const int rloc = wid * 16 + g;        // local row (and rloc+8)
    const float scale = 0.125f;           // 1/sqrt(64)

    for (int j = 0; j <= qi; j++) {
        // Load K,V tiles (64x64 each)
        for (int i = tid; i < 1024; i += 128) {
            int r = i >> 4, c = (i & 15) << 2;
            float4 kv = *(const float4*)&Kg[((size_t)j * 64 + r) * D_ + c];
            Ks[r * SMS + c + 0] = tf32_round(kv.x);
            Ks[r * SMS + c + 1] = tf32_round(kv.y);
            Ks[r * SMS + c + 2] = tf32_round(kv.z);
            Ks[r * SMS + c + 3] = tf32_round(kv.w);
            float4 vv = *(const float4*)&Vg[((size_t)j * 64 + r) * D_ + c];
            Vs[r * SMS + c + 0] = tf32_round(vv.x);
            Vs[r * SMS + c + 1] = tf32_round(vv.y);
            Vs[r * SMS + c + 2] = tf32_round(vv.z);
            Vs[r * SMS + c + 3] = tf32_round(vv.w);
        }
        __syncthreads();

        // S = Q K^T  (16 rows per warp x 64 kv)
        float sfr[8][4];
#pragma unroll
        for (int ni = 0; ni < 8; ni++)
#pragma unroll
            for (int r = 0; r < 4; r++) sfr[ni][r] = 0.0f;

#pragma unroll
        for (int kk = 0; kk < 8; kk++) {
            uint32_t af[4];
            af[0] = __float_as_uint(Qs[(rloc    ) * SMS + kk * 8 + tg    ]);
            af[1] = __float_as_uint(Qs[(rloc + 8) * SMS + kk * 8 + tg    ]);
            af[2] = __float_as_uint(Qs[(rloc    ) * SMS + kk * 8 + tg + 4]);
            af[3] = __float_as_uint(Qs[(rloc + 8) * SMS + kk * 8 + tg + 4]);
#pragma unroll
            for (int ni = 0; ni < 8; ni++) {
                uint32_t bf[2];
                bf[0] = __float_as_uint(Ks[(ni * 8 + g) * SMS + kk * 8 + tg    ]);
                bf[1] = __float_as_uint(Ks[(ni * 8 + g) * SMS + kk * 8 + tg + 4]);
                mma_tf32(sfr[ni], af, bf, sfr[ni]);
            }
        }

        // Scale + causal mask (only diagonal tile needs masking)
        const bool diag = (j == qi);
        const int rowg0 = qi * 64 + rloc;
        const int rowg1 = rowg0 + 8;
#pragma unroll
        for (int ni = 0; ni < 8; ni++) {
#pragma unroll
            for (int r = 0; r < 4; r++) {
                float s = sfr[ni][r] * scale;
                if (diag) {
                    int colg = j * 64 + ni * 8 + tg * 2 + (r & 1);
                    int rowg = (r >> 1) ? rowg1 : rowg0;
                    if (colg > rowg) s = -1e30f;
                }
                sfr[ni][r] = s;
            }
        }

        // Online softmax (two rows per thread)
        float mx0 = -1e30f, mx1 = -1e30f;
#pragma unroll
        for (int ni = 0; ni < 8; ni++) {
            mx0 = fmaxf(mx0, fmaxf(sfr[ni][0], sfr[ni][1]));
            mx1 = fmaxf(mx1, fmaxf(sfr[ni][2], sfr[ni][3]));
        }
        mx0 = fmaxf(mx0, __shfl_xor_sync(0xffffffffu, mx0, 1));
        mx0 = fmaxf(mx0, __shfl_xor_sync(0xffffffffu, mx0, 2));
        mx1 = fmaxf(mx1, __shfl_xor_sync(0xffffffffu, mx1, 1));
        mx1 = fmaxf(mx1, __shfl_xor_sync(0xffffffffu, mx1, 2));

        float mn0 = fmaxf(mrow0, mx0);
        float mn1 = fmaxf(mrow1, mx1);
        float a0 = __expf(mrow0 - mn0);
        float a1 = __expf(mrow1 - mn1);

        float rs0 = 0.0f, rs1 = 0.0f;
#pragma unroll
        for (int ni = 0; ni < 8; ni++) {
            float p0 = __expf(sfr[ni][0] - mn0); sfr[ni][0] = p0; rs0 += p0;
            float p1 = __expf(sfr[ni][1] - mn0); sfr[ni][1] = p1; rs0 += p1;
            float p2 = __expf(sfr[ni][2] - mn1); sfr[ni][2] = p2; rs1 += p2;
            float p3 = __expf(sfr[ni][3] - mn1); sfr[ni][3] = p3; rs1 += p3;
        }
        rs0 += __shfl_xor_sync(0xffffffffu, rs0, 1);
        rs0 += __shfl_xor_sync(0xffffffffu, rs0, 2);
        rs1 += __shfl_xor_sync(0xffffffffu, rs1, 1);
        rs1 += __shfl_xor_sync(0xffffffffu, rs1, 2);

        lrow0 = lrow0 * a0 + rs0;
        lrow1 = lrow1 * a1 + rs1;
        mrow0 = mn0;
        mrow1 = mn1;

        // Rescale O
#pragma unroll
        for (int ni = 0; ni < 8; ni++) {
            O[ni][0] *= a0; O[ni][1] *= a0;
            O[ni][2] *= a1; O[ni][3] *= a1;
        }

        // Write P to smem (each warp writes only its own 16-row slab)
#pragma unroll
        for (int ni = 0; ni < 8; ni++) {
            int c = ni * 8 + tg * 2;
            Ps[(rloc    ) * SMS + c    ] = tf32_round(sfr[ni][0]);
            Ps[(rloc    ) * SMS + c + 1] = tf32_round(sfr[ni][1]);
            Ps[(rloc + 8) * SMS + c    ] = tf32_round(sfr[ni][2]);
            Ps[(rloc + 8) * SMS + c + 1] = tf32_round(sfr[ni][3]);
        }
        __syncwarp();

        // O += P @ V
#pragma unroll
        for (int kk = 0; kk < 8; kk++) {
            uint32_t af[4];
            af[0] = __float_as_uint(Ps[(rloc    ) * SMS + kk * 8 + tg    ]);
            af[1] = __float_as_uint(Ps[(rloc + 8) * SMS + kk * 8 + tg    ]);
            af[2] = __float_as_uint(Ps[(rloc    ) * SMS + kk * 8 + tg + 4]);
            af[3] = __float_as_uint(Ps[(rloc + 8) * SMS + kk * 8 + tg + 4]);
#pragma unroll
            for (int ni = 0; ni < 8; ni++) {
                uint32_t bf[2];
                bf[0] = __float_as_uint(Vs[(kk * 8 + tg    ) * SMS + ni * 8 + g]);
                bf[1] = __float_as_uint(Vs[(kk * 8 + tg + 4) * SMS + ni * 8 + g]);
                mma_tf32(O[ni], af, bf, O[ni]);
            }
        }
        __syncthreads();   // before next iter overwrites K/V
    }

    // Epilogue: O /= l, write to y in [B,T,H,D] layout
    float il0 = 1.0f / lrow0;
    float il1 = 1.0f / lrow1;
    int t0 = qi * 64 + rloc;
#pragma unroll
    for (int ni = 0; ni < 8; ni++) {
        int d = ni * 8 + tg * 2;
        size_t base0 = ((size_t)(b * T_ + t0    ) * H_ + h) * D_ + d;
        size_t base1 = ((size_t)(b * T_ + t0 + 8) * H_ + h) * D_ + d;
        float2 v0 = make_float2(O[ni][0] * il0, O[ni][1] * il0);
        float2 v1 = make_float2(O[ni][2] * il1, O[ni][3] * il1);
        *(float2*)&g_y[base0] = v0;
        *(float2*)&g_y[base1] = v1;
    }
}

// ---------------------------------------------------------------------------
// Launch
// ---------------------------------------------------------------------------
extern "C" void kernel_launch(void* const* d_in, const int* in_sizes, int n_in,
                              void* d_out, int out_size)
{
    const float* x     = (const float*)d_in[0];
    const float* Wqkv  = (const float*)d_in[1];
    const float* bqkv  = (const float*)d_in[2];
    const float* Wout  = (const float*)d_in[3];
    const float* bout  = (const float*)d_in[4];
    float* out = (float*)d_out;

    float* yptr = nullptr;
    cudaGetSymbolAddress((void**)&yptr, g_y);

    cudaFuncSetAttribute(attn_kernel,
                         cudaFuncAttributeMaxDynamicSharedMemorySize, ATTN_SMEM);

    // 1) QKV projection: [8192,1024] @ [1024,3072] -> scatter q/k/v [B,H,T,D]
    gemm_tf32_kernel<0><<<dim3(3 * C_ / 128, B_ * T_ / 128), 256>>>(
        x, Wqkv, bqkv, nullptr, B_ * T_, 3 * C_, C_);

    // 2) Causal flash attention -> y [B,T,C]
    attn_kernel<<<dim3(BH_, T_ / 64), 128, ATTN_SMEM>>>();

    // 3) Output projection: [8192,1024] @ [1024,1024] + b -> out
    gemm_tf32_kernel<1><<<dim3(C_ / 128, B_ * T_ / 128), 256>>>(
        yptr, Wout, bout, out, B_ * T_, C_, C_);
}

// round 2
// speedup vs baseline: 1.1254x; 1.1254x over previous
#include <cuda_runtime.h>
#include <cstdint>
#include <math.h>

// Problem constants
#define B_ 4
#define T_ 2048
#define C_ 1024
#define H_ 16
#define D_ 64
#define BH_ (B_ * H_)

// Scratch (device globals -- no allocation allowed)
__device__ float g_q[BH_ * T_ * D_];   // [B,H,T,D]
__device__ float g_k[BH_ * T_ * D_];
__device__ float g_v[BH_ * T_ * D_];
__device__ float g_y[B_ * T_ * C_];    // [B,T,H,D] = [B,T,C]

// ---------------------------------------------------------------------------
// Helpers
// ---------------------------------------------------------------------------
__device__ __forceinline__ float tf32_round(float x) {
    uint32_t u;
    asm("cvt.rna.tf32.f32 %0, %1;" : "=r"(u) : "f"(x));
    return __uint_as_float(u);
}

__device__ __forceinline__ void mma_tf32(float d[4], const uint32_t a[4],
                                         const uint32_t b[2], const float c[4]) {
    asm volatile(
        "mma.sync.aligned.m16n8k8.row.col.f32.tf32.tf32.f32 "
        "{%0,%1,%2,%3},{%4,%5,%6,%7},{%8,%9},{%10,%11,%12,%13};"
        : "=f"(d[0]), "=f"(d[1]), "=f"(d[2]), "=f"(d[3])
        : "r"(a[0]), "r"(a[1]), "r"(a[2]), "r"(a[3]),
          "r"(b[0]), "r"(b[1]),
          "f"(c[0]), "f"(c[1]), "f"(c[2]), "f"(c[3]));
}

__device__ __forceinline__ uint32_t smem_u32(const void* p) {
    return (uint32_t)__cvta_generic_to_shared(p);
}

// ldmatrix x4: four 8x8 b16 matrices; for tf32 each 16B row = 4 elements, and
// lane l receives element (row=l>>2, col=l&3) of its matrix -> exact tf32
// m16n8k8 A-fragment layout when matrices are ordered (rlo,klo),(rhi,klo),
// (rlo,khi),(rhi,khi).
__device__ __forceinline__ void ldsm_x4(uint32_t d[4], uint32_t saddr) {
    asm volatile(
        "ldmatrix.sync.aligned.m8n8.x4.shared.b16 {%0,%1,%2,%3}, [%4];"
        : "=r"(d[0]), "=r"(d[1]), "=r"(d[2]), "=r"(d[3]) : "r"(saddr));
}

// ---------------------------------------------------------------------------
// TF32 GEMM: C[M,N] = A[M,K] @ W[K,N] + bias
// BM=128 BN=128 BK=32, 256 threads (8 warps, 2x4), warp tile 64x32.
// Double-buffered smem, register-staged global loads.
// A smem: 128 rows x 32 floats, XOR-swizzled 16B groups (LDSM + STS.128 CF).
// B smem: 32 rows x pitch 136 (scalar b-frag LDS conflict-free: banks tg*8+g).
// MODE 0: scatter epilogue into g_q/g_k/g_v. MODE 1: row-major + bias.
// ---------------------------------------------------------------------------
#define GEMM_SMEM ((2 * 4096 + 2 * 4352) * 4)   // 67584 bytes

template <int MODE>
__global__ __launch_bounds__(256, 2) void gemm_tf32_kernel(
    const float* __restrict__ A, const float* __restrict__ W,
    const float* __restrict__ bias, float* __restrict__ Cout,
    int M, int N, int K)
{
    extern __shared__ float sm[];
    float* As0 = sm;
    float* As1 = sm + 4096;
    float* Bs0 = sm + 8192;
    float* Bs1 = sm + 8192 + 4352;

    const int tid  = threadIdx.x;
    const int lane = tid & 31;
    const int wid  = tid >> 5;
    const int g    = lane >> 2;
    const int tg   = lane & 3;
    const int wr   = (wid >> 2) * 64;
    const int wc   = (wid & 3) * 32;
    const int m0   = blockIdx.y * 128;
    const int n0   = blockIdx.x * 128;

    // loader coords: A tile 128x32 as 1024 float4 (4/thread), B tile 32x128 same
    const int la_r  = tid >> 3;          // + i*32
    const int la_g  = tid & 7;           // 16B group in row
    const int lb_k  = tid >> 5;          // + i*8
    const int lb_n4 = (tid & 31) << 2;

    // LDSM lane constants
    const int lrow = lane & 15;          // row within 16-row tile
    const int jj   = lane >> 4;          // k-half select
    const int xr   = lrow & 7;           // swizzle key

    float acc[4][4][4];
#pragma unroll
    for (int mi = 0; mi < 4; mi++)
#pragma unroll
        for (int ni = 0; ni < 4; ni++)
#pragma unroll
            for (int r = 0; r < 4; r++) acc[mi][ni][r] = 0.0f;

    const uint32_t asb0 = smem_u32(As0) + ((wr + lrow) << 7);
    const uint32_t asb1 = smem_u32(As1) + ((wr + lrow) << 7);

    float4 ra[4], rb[4];

    auto ldg_tile = [&](int k0) {
#pragma unroll
        for (int i = 0; i < 4; i++) {
            int r = la_r + i * 32;
            ra[i] = *(const float4*)&A[(size_t)(m0 + r) * K + k0 + (la_g << 2)];
            int kr = lb_k + i * 8;
            rb[i] = *(const float4*)&W[(size_t)(k0 + kr) * N + n0 + lb_n4];
        }
    };
    auto sts_tile = [&](float* Ad, float* Bd) {
#pragma unroll
        for (int i = 0; i < 4; i++) {
            int r = la_r + i * 32;
            float4 v = ra[i];
            v.x = tf32_round(v.x); v.y = tf32_round(v.y);
            v.z = tf32_round(v.z); v.w = tf32_round(v.w);
            *(float4*)&Ad[r * 32 + ((la_g ^ (r & 7)) << 2)] = v;
            int kr = lb_k + i * 8;
            float4 w4 = rb[i];
            w4.x = tf32_round(w4.x); w4.y = tf32_round(w4.y);
            w4.z = tf32_round(w4.z); w4.w = tf32_round(w4.w);
            *(float4*)&Bd[kr * 136 + lb_n4] = w4;
        }
    };

    // prologue
    ldg_tile(0);
    sts_tile(As0, Bs0);
    __syncthreads();

    const int KT = K >> 5;
    for (int kt = 0; kt < KT; kt++) {
        const int cur = kt & 1;
        if (kt + 1 < KT) ldg_tile((kt + 1) << 5);

        const float* Bb = cur ? Bs1 : Bs0;
        const uint32_t abase = cur ? asb1 : asb0;

#pragma unroll
        for (int kk = 0; kk < 4; kk++) {
            uint32_t af[4][4];
#pragma unroll
            for (int mi = 0; mi < 4; mi++) {
                uint32_t addr = abase + (mi << 11) +
                                ((((kk << 1) | jj) ^ xr) << 4);
                ldsm_x4(af[mi], addr);
            }
            uint32_t bf[4][2];
#pragma unroll
            for (int ni = 0; ni < 4; ni++) {
                int c = wc + ni * 8 + g;
                bf[ni][0] = __float_as_uint(Bb[(kk * 8 + tg    ) * 136 + c]);
                bf[ni][1] = __float_as_uint(Bb[(kk * 8 + tg + 4) * 136 + c]);
            }
#pragma unroll
            for (int mi = 0; mi < 4; mi++)
#pragma unroll
                for (int ni = 0; ni < 4; ni++)
                    mma_tf32(acc[mi][ni], af[mi], bf[ni], acc[mi][ni]);
        }

        if (kt + 1 < KT) {
            sts_tile((cur ? As0 : As1), (cur ? Bs0 : Bs1));
        }
        __syncthreads();
    }

    // Epilogue
#pragma unroll
    for (int mi = 0; mi < 4; mi++) {
#pragma unroll
        for (int ni = 0; ni < 4; ni++) {
#pragma unroll
            for (int r = 0; r < 4; r++) {
                int row = m0 + wr + mi * 16 + g + ((r >> 1) ? 8 : 0);
                int col = n0 + wc + ni * 8 + tg * 2 + (r & 1);
                float v = acc[mi][ni][r] + bias[col];
                if (MODE == 0) {
                    int b = row >> 11;
                    int t = row & (T_ - 1);
                    int which = col >> 10;
                    int rr = col & (C_ - 1);
                    int h = rr >> 6;
                    int d = rr & 63;
                    float* dst = (which == 0) ? g_q : (which == 1) ? g_k : g_v;
                    dst[(((size_t)(b * H_ + h)) * T_ + t) * D_ + d] = v;
                } else {
                    Cout[(size_t)row * N + col] = v;
                }
            }
        }
    }
}

// ---------------------------------------------------------------------------
// Flash attention (causal), TF32 mma, BQ=128 BKV=64, 256 threads (8 warps),
// each warp owns a 16-row slab of Q. D = 64. Pitch 72 (V-frag LDS CF).
// ---------------------------------------------------------------------------
#define SMS 72
#define ATTN_SMEM ((128 + 64 + 64 + 128) * SMS * 4)   // 110592 bytes

__global__ __launch_bounds__(256, 1) void attn_kernel()
{
    extern __shared__ float sm[];
    float* Qs = sm;                       // 128 x SMS
    float* Ks = sm + 128 * SMS;           // 64 x SMS
    float* Vs = Ks + 64 * SMS;            // 64 x SMS
    float* Ps = Vs + 64 * SMS;            // 128 x SMS

    const int bh  = blockIdx.x;
    const int b   = bh >> 4;
    const int h   = bh & 15;
    const int qi  = blockIdx.y;           // 128-row q tile index
    const int tid = threadIdx.x;
    const int lane = tid & 31;
    const int wid  = tid >> 5;
    const int g    = lane >> 2;
    const int tg   = lane & 3;

    const float* Qg = g_q + ((size_t)bh * T_ + qi * 128) * D_;
    const float* Kg = g_k + (size_t)bh * T_ * D_;
    const float* Vg = g_v + (size_t)bh * T_ * D_;

    // Load Q tile (128x64)
    for (int i = tid; i < 2048; i += 256) {
        int r = i >> 4, c = (i & 15) << 2;
        float4 v = *(const float4*)&Qg[r * D_ + c];
        Qs[r * SMS + c + 0] = tf32_round(v.x);
        Qs[r * SMS + c + 1] = tf32_round(v.y);
        Qs[r * SMS + c + 2] = tf32_round(v.z);
        Qs[r * SMS + c + 3] = tf32_round(v.w);
    }

    float O[8][4];
#pragma unroll
    for (int ni = 0; ni < 8; ni++)
#pragma unroll
        for (int r = 0; r < 4; r++) O[ni][r] = 0.0f;
    float mrow0 = -1e30f, mrow1 = -1e30f;
    float lrow0 = 0.0f,   lrow1 = 0.0f;

    const int rloc = wid * 16 + g;        // local q row (and rloc+8)
    const float scale = 0.125f;           // 1/sqrt(64)
    const int jmax = 2 * qi + 1;

    for (int j = 0; j <= jmax; j++) {
        // Load K,V tiles (64x64 each)
        for (int i = tid; i < 1024; i += 256) {
            int r = i >> 4, c = (i & 15) << 2;
            float4 kv = *(const float4*)&Kg[((size_t)j * 64 + r) * D_ + c];
            Ks[r * SMS + c + 0] = tf32_round(kv.x);
            Ks[r * SMS + c + 1] = tf32_round(kv.y);
            Ks[r * SMS + c + 2] = tf32_round(kv.z);
            Ks[r * SMS + c + 3] = tf32_round(kv.w);
            float4 vv = *(const float4*)&Vg[((size_t)j * 64 + r) * D_ + c];
            Vs[r * SMS + c + 0] = tf32_round(vv.x);
            Vs[r * SMS + c + 1] = tf32_round(vv.y);
            Vs[r * SMS + c + 2] = tf32_round(vv.z);
            Vs[r * SMS + c + 3] = tf32_round(vv.w);
        }
        __syncthreads();

        // S = Q K^T
        float sfr[8][4];
#pragma unroll
        for (int ni = 0; ni < 8; ni++)
#pragma unroll
            for (int r = 0; r < 4; r++) sfr[ni][r] = 0.0f;

#pragma unroll
        for (int kk = 0; kk < 8; kk++) {
            uint32_t af[4];
            af[0] = __float_as_uint(Qs[(rloc    ) * SMS + kk * 8 + tg    ]);
            af[1] = __float_as_uint(Qs[(rloc + 8) * SMS + kk * 8 + tg    ]);
            af[2] = __float_as_uint(Qs[(rloc    ) * SMS + kk * 8 + tg + 4]);
            af[3] = __float_as_uint(Qs[(rloc + 8) * SMS + kk * 8 + tg + 4]);
#pragma unroll
            for (int ni = 0; ni < 8; ni++) {
                uint32_t bf[2];
                bf[0] = __float_as_uint(Ks[(ni * 8 + g) * SMS + kk * 8 + tg    ]);
                bf[1] = __float_as_uint(Ks[(ni * 8 + g) * SMS + kk * 8 + tg + 4]);
                mma_tf32(sfr[ni], af, bf, sfr[ni]);
            }
        }

        // Scale + causal mask (last two kv tiles straddle the diagonal)
        const bool diag = (j >= 2 * qi);
        const int rowg0 = qi * 128 + rloc;
        const int rowg1 = rowg0 + 8;
#pragma unroll
        for (int ni = 0; ni < 8; ni++) {
#pragma unroll
            for (int r = 0; r < 4; r++) {
                float s = sfr[ni][r] * scale;
                if (diag) {
                    int colg = j * 64 + ni * 8 + tg * 2 + (r & 1);
                    int rowg = (r >> 1) ? rowg1 : rowg0;
                    if (colg > rowg) s = -1e30f;
                }
                sfr[ni][r] = s;
            }
        }

        // Online softmax
        float mx0 = -1e30f, mx1 = -1e30f;
#pragma unroll
        for (int ni = 0; ni < 8; ni++) {
            mx0 = fmaxf(mx0, fmaxf(sfr[ni][0], sfr[ni][1]));
            mx1 = fmaxf(mx1, fmaxf(sfr[ni][2], sfr[ni][3]));
        }
        mx0 = fmaxf(mx0, __shfl_xor_sync(0xffffffffu, mx0, 1));
        mx0 = fmaxf(mx0, __shfl_xor_sync(0xffffffffu, mx0, 2));
        mx1 = fmaxf(mx1, __shfl_xor_sync(0xffffffffu, mx1, 1));
        mx1 = fmaxf(mx1, __shfl_xor_sync(0xffffffffu, mx1, 2));

        float mn0 = fmaxf(mrow0, mx0);
        float mn1 = fmaxf(mrow1, mx1);
        float a0 = __expf(mrow0 - mn0);
        float a1 = __expf(mrow1 - mn1);

        float rs0 = 0.0f, rs1 = 0.0f;
#pragma unroll
        for (int ni = 0; ni < 8; ni++) {
            float p0 = __expf(sfr[ni][0] - mn0); sfr[ni][0] = p0; rs0 += p0;
            float p1 = __expf(sfr[ni][1] - mn0); sfr[ni][1] = p1; rs0 += p1;
            float p2 = __expf(sfr[ni][2] - mn1); sfr[ni][2] = p2; rs1 += p2;
            float p3 = __expf(sfr[ni][3] - mn1); sfr[ni][3] = p3; rs1 += p3;
        }
        rs0 += __shfl_xor_sync(0xffffffffu, rs0, 1);
        rs0 += __shfl_xor_sync(0xffffffffu, rs0, 2);
        rs1 += __shfl_xor_sync(0xffffffffu, rs1, 1);
        rs1 += __shfl_xor_sync(0xffffffffu, rs1, 2);

        lrow0 = lrow0 * a0 + rs0;
        lrow1 = lrow1 * a1 + rs1;
        mrow0 = mn0;
        mrow1 = mn1;

#pragma unroll
        for (int ni = 0; ni < 8; ni++) {
            O[ni][0] *= a0; O[ni][1] *= a0;
            O[ni][2] *= a1; O[ni][3] *= a1;
        }

        // P to smem (warp-private 16-row slab)
#pragma unroll
        for (int ni = 0; ni < 8; ni++) {
            int c = ni * 8 + tg * 2;
            Ps[(rloc    ) * SMS + c    ] = tf32_round(sfr[ni][0]);
            Ps[(rloc    ) * SMS + c + 1] = tf32_round(sfr[ni][1]);
            Ps[(rloc + 8) * SMS + c    ] = tf32_round(sfr[ni][2]);
            Ps[(rloc + 8) * SMS + c + 1] = tf32_round(sfr[ni][3]);
        }
        __syncwarp();

        // O += P @ V
#pragma unroll
        for (int kk = 0; kk < 8; kk++) {
            uint32_t af[4];
            af[0] = __float_as_uint(Ps[(rloc    ) * SMS + kk * 8 + tg    ]);
            af[1] = __float_as_uint(Ps[(rloc + 8) * SMS + kk * 8 + tg    ]);
            af[2] = __float_as_uint(Ps[(rloc    ) * SMS + kk * 8 + tg + 4]);
            af[3] = __float_as_uint(Ps[(rloc + 8) * SMS + kk * 8 + tg + 4]);
#pragma unroll
            for (int ni = 0; ni < 8; ni++) {
                uint32_t bf[2];
                bf[0] = __float_as_uint(Vs[(kk * 8 + tg    ) * SMS + ni * 8 + g]);
                bf[1] = __float_as_uint(Vs[(kk * 8 + tg + 4) * SMS + ni * 8 + g]);
                mma_tf32(O[ni], af, bf, O[ni]);
            }
        }
        __syncthreads();
    }

    // Epilogue
    float il0 = 1.0f / lrow0;
    float il1 = 1.0f / lrow1;
    int t0 = qi * 128 + rloc;
#pragma unroll
    for (int ni = 0; ni < 8; ni++) {
        int d = ni * 8 + tg * 2;
        size_t base0 = ((size_t)(b * T_ + t0    ) * H_ + h) * D_ + d;
        size_t base1 = ((size_t)(b * T_ + t0 + 8) * H_ + h) * D_ + d;
        float2 v0 = make_float2(O[ni][0] * il0, O[ni][1] * il0);
        float2 v1 = make_float2(O[ni][2] * il1, O[ni][3] * il1);
        *(float2*)&g_y[base0] = v0;
        *(float2*)&g_y[base1] = v1;
    }
}

// ---------------------------------------------------------------------------
// Launch
// ---------------------------------------------------------------------------
extern "C" void kernel_launch(void* const* d_in, const int* in_sizes, int n_in,
                              void* d_out, int out_size)
{
    const float* x     = (const float*)d_in[0];
    const float* Wqkv  = (const float*)d_in[1];
    const float* bqkv  = (const float*)d_in[2];
    const float* Wout  = (const float*)d_in[3];
    const float* bout  = (const float*)d_in[4];
    float* out = (float*)d_out;

    float* yptr = nullptr;
    cudaGetSymbolAddress((void**)&yptr, g_y);

    cudaFuncSetAttribute(gemm_tf32_kernel<0>,
                         cudaFuncAttributeMaxDynamicSharedMemorySize, GEMM_SMEM);
    cudaFuncSetAttribute(gemm_tf32_kernel<1>,
                         cudaFuncAttributeMaxDynamicSharedMemorySize, GEMM_SMEM);
    cudaFuncSetAttribute(attn_kernel,
                         cudaFuncAttributeMaxDynamicSharedMemorySize, ATTN_SMEM);

    // 1) QKV projection
    gemm_tf32_kernel<0><<<dim3(3 * C_ / 128, B_ * T_ / 128), 256, GEMM_SMEM>>>(
        x, Wqkv, bqkv, nullptr, B_ * T_, 3 * C_, C_);

    // 2) Causal flash attention
    attn_kernel<<<dim3(BH_, T_ / 128), 256, ATTN_SMEM>>>();

    // 3) Output projection
    gemm_tf32_kernel<1><<<dim3(C_ / 128, B_ * T_ / 128), 256, GEMM_SMEM>>>(
        yptr, Wout, bout, out, B_ * T_, C_, C_);
}

// round 4
// speedup vs baseline: 1.6588x; 1.4740x over previous
#include <cuda_runtime.h>
#include <cstdint>
#include <math.h>

// Problem constants
#define B_ 4
#define T_ 2048
#define C_ 1024
#define H_ 16
#define D_ 64
#define BH_ (B_ * H_)

// Scratch (device globals -- no allocation allowed)
__device__ float g_q[BH_ * T_ * D_];    // [B,H,T,D]
__device__ float g_k[BH_ * T_ * D_];
__device__ float g_v[BH_ * T_ * D_];
__device__ float g_y[B_ * T_ * C_];     // [B,T,C], tf32-rounded by attn epilogue
__device__ float g_x[B_ * T_ * C_];     // tf32-rounded x
__device__ float g_wqkvT[3 * C_ * C_];  // [3C, C] = W_qkv^T, tf32-rounded
__device__ float g_woutT[C_ * C_];      // [C, C]  = W_out^T, tf32-rounded

// ---------------------------------------------------------------------------
// Helpers
// ---------------------------------------------------------------------------
__device__ __forceinline__ float tf32_round(float x) {
    uint32_t u;
    asm("cvt.rna.tf32.f32 %0, %1;" : "=r"(u) : "f"(x));
    return __uint_as_float(u);
}

__device__ __forceinline__ uint32_t smem_u32(const void* p) {
    return (uint32_t)__cvta_generic_to_shared(p);
}

__device__ __forceinline__ void mma_tf32(float d[4], const uint32_t a[4],
                                         const uint32_t b[2], const float c[4]) {
    asm volatile(
        "mma.sync.aligned.m16n8k8.row.col.f32.tf32.tf32.f32 "
        "{%0,%1,%2,%3},{%4,%5,%6,%7},{%8,%9},{%10,%11,%12,%13};"
        : "=f"(d[0]), "=f"(d[1]), "=f"(d[2]), "=f"(d[3])
        : "r"(a[0]), "r"(a[1]), "r"(a[2]), "r"(a[3]),
          "r"(b[0]), "r"(b[1]),
          "f"(c[0]), "f"(c[1]), "f"(c[2]), "f"(c[3]));
}

__device__ __forceinline__ void ldsm_x4(uint32_t d[4], uint32_t saddr) {
    asm volatile(
        "ldmatrix.sync.aligned.m8n8.x4.shared.b16 {%0,%1,%2,%3}, [%4];"
        : "=r"(d[0]), "=r"(d[1]), "=r"(d[2]), "=r"(d[3]) : "r"(saddr));
}

__device__ __forceinline__ void cp_async16(uint32_t dst, const void* src) {
    asm volatile("cp.async.cg.shared.global [%0], [%1], 16;"
                 :: "r"(dst), "l"(src) : "memory");
}
__device__ __forceinline__ void cp_commit() {
    asm volatile("cp.async.commit_group;" ::: "memory");
}
template <int N>
__device__ __forceinline__ void cp_wait() {
    asm volatile("cp.async.wait_group %0;" :: "n"(N) : "memory");
}

// ---------------------------------------------------------------------------
// Prep kernels: tf32-round x; transpose+round W matrices
// ---------------------------------------------------------------------------
__global__ void round_copy(const float* __restrict__ in, float* __restrict__ out, int n4) {
    int i = blockIdx.x * blockDim.x + threadIdx.x;
    if (i < n4) {
        float4 v = ((const float4*)in)[i];
        v.x = tf32_round(v.x); v.y = tf32_round(v.y);
        v.z = tf32_round(v.z); v.w = tf32_round(v.w);
        ((float4*)out)[i] = v;
    }
}

// in: [R, Ccols] row-major -> out: [Ccols, R] row-major, tf32-rounded
__global__ void transpose_round(const float* __restrict__ in, float* __restrict__ out,
                                int R, int Ccols) {
    __shared__ float t[32][33];
    int bx = blockIdx.x * 32;
    int by = blockIdx.y * 32;
    int x = threadIdx.x, y = threadIdx.y;
#pragma unroll
    for (int j = 0; j < 32; j += 8)
        t[y + j][x] = in[(size_t)(by + y + j) * Ccols + bx + x];
    __syncthreads();
#pragma unroll
    for (int j = 0; j < 32; j += 8)
        out[(size_t)(bx + y + j) * R + by + x] = tf32_round(t[x][y + j]);
}

// ---------------------------------------------------------------------------
// TF32 GEMM: C[M, N] = A[M, 1024] @ Bt[N, 1024]^T + bias
// A, Bt pre-rounded tf32, K-major. BM=128 BN=128 BK=32, 256 threads (8 warps
// 2x4), warp tile 64x32. cp.async 3-stage pipeline, 1 sync per k-tile.
// Both fragments via ldmatrix from swizzled 128B-row tiles.
// MODE 0: scatter into g_q/g_k/g_v. MODE 1: row-major store + bias.
// ---------------------------------------------------------------------------
#define GKT 32                   // k-tiles (K=1024 / 32)
#define STAGE_B 16384            // one operand tile: 128 rows x 128B
#define GEMM_SMEM (6 * STAGE_B)  // 3 stages x (A+B) = 98304

template <int MODE>
__global__ __launch_bounds__(256, 2) void gemm_tf32(
    const float* __restrict__ Ag, const float* __restrict__ Bg,
    const float* __restrict__ bias, float* __restrict__ Cout, int N)
{
    extern __shared__ char smem[];
    const uint32_t sA = smem_u32(smem);              // 3 x STAGE_B
    const uint32_t sB = sA + 3 * STAGE_B;            // 3 x STAGE_B

    const int tid  = threadIdx.x;
    const int lane = tid & 31;
    const int wid  = tid >> 5;
    const int wr   = (wid >> 2) * 64;                // warp row offset
    const int wc   = (wid & 3) * 32;                 // warp col offset
    const int m0   = blockIdx.y * 128;
    const int n0   = blockIdx.x * 128;

    // cp.async loader: 1024 16B-chunks per tile, 4 per thread
    const int lr = tid >> 3;          // row (step 32? no: rows 0..127 via +32*i)
    const int lg = tid & 7;           // 16B group in row

    auto issue = [&](int kt) {
        const int s = kt % 3;
#pragma unroll
        for (int i = 0; i < 4; i++) {
            int r = lr + i * 32;
            uint32_t off = r * 128 + ((lg ^ (r & 7)) << 4);
            cp_async16(sA + s * STAGE_B + off,
                       Ag + (size_t)(m0 + r) * 1024 + kt * 32 + lg * 4);
            cp_async16(sB + s * STAGE_B + off,
                       Bg + (size_t)(n0 + r) * 1024 + kt * 32 + lg * 4);
        }
        cp_commit();
    };

    // fragment lane mapping
    const int arow = wr + (lane & 7) + 8 * ((lane >> 3) & 1);  // A rows
    const int kha  = lane >> 4;                                 // A k-half
    const int brow0 = wc + (lane & 7) + 8 * (lane >> 4);        // B rows (pair 0)
    const int khb  = (lane >> 3) & 1;                           // B k-half

    float acc[4][4][4];
#pragma unroll
    for (int mi = 0; mi < 4; mi++)
#pragma unroll
        for (int ni = 0; ni < 4; ni++)
#pragma unroll
            for (int r = 0; r < 4; r++) acc[mi][ni][r] = 0.0f;

    issue(0);
    issue(1);

    for (int kt = 0; kt < GKT; kt++) {
        if (kt + 1 < GKT) cp_wait<1>(); else cp_wait<0>();
        __syncthreads();
        if (kt + 2 < GKT) issue(kt + 2);

        const int s = kt % 3;
        const uint32_t aS = sA + s * STAGE_B;
        const uint32_t bS = sB + s * STAGE_B;

#pragma unroll
        for (int kk = 0; kk < 4; kk++) {
            uint32_t af[4][4];
#pragma unroll
            for (int mi = 0; mi < 4; mi++) {
                int r = arow + mi * 16;
                uint32_t addr = aS + r * 128 +
                                ((((kk << 1) | kha) ^ (r & 7)) << 4);
                ldsm_x4(af[mi], addr);
            }
            uint32_t bf[4][2];
#pragma unroll
            for (int p = 0; p < 2; p++) {
                int r = brow0 + p * 16;
                uint32_t addr = bS + r * 128 +
                                ((((kk << 1) | khb) ^ (r & 7)) << 4);
                uint32_t d[4];
                ldsm_x4(d, addr);
                bf[2 * p][0] = d[0]; bf[2 * p][1] = d[1];
                bf[2 * p + 1][0] = d[2]; bf[2 * p + 1][1] = d[3];
            }
#pragma unroll
            for (int mi = 0; mi < 4; mi++)
#pragma unroll
                for (int ni = 0; ni < 4; ni++)
                    mma_tf32(acc[mi][ni], af[mi], bf[ni], acc[mi][ni]);
        }
        __syncthreads();
    }

    // Epilogue
    const int g  = lane >> 2;
    const int tg = lane & 3;
#pragma unroll
    for (int mi = 0; mi < 4; mi++) {
#pragma unroll
        for (int ni = 0; ni < 4; ni++) {
#pragma unroll
            for (int r = 0; r < 4; r++) {
                int row = m0 + wr + mi * 16 + g + ((r >> 1) ? 8 : 0);
                int col = n0 + wc + ni * 8 + tg * 2 + (r & 1);
                float v = acc[mi][ni][r] + __ldg(&bias[col]);
                if (MODE == 0) {
                    int b = row >> 11;
                    int t = row & (T_ - 1);
                    int which = col >> 10;
                    int rr = col & (C_ - 1);
                    int h = rr >> 6;
                    int d = rr & 63;
                    float* dst = (which == 0) ? g_q : (which == 1) ? g_k : g_v;
                    dst[(((size_t)(b * H_ + h)) * T_ + t) * D_ + d] = v;
                } else {
                    Cout[(size_t)row * N + col] = v;
                }
            }
        }
    }
}

// ---------------------------------------------------------------------------
// Flash attention (causal), TF32 mma.sync, BQ=64 BKV=64, 128 threads (4 warps).
// Q/K/P fragments via ldmatrix (pitch 68 = CF for ldsm); V scalar (pitch 72).
// ---------------------------------------------------------------------------
#define PQ 68                          // pitch for Qs/Ks/Ps (floats)
#define PV 72                          // pitch for Vs
#define ATTN_SMEM ((3 * 64 * PQ + 64 * PV) * 4)   // 70656 bytes

__global__ __launch_bounds__(128) void attn_kernel()
{
    extern __shared__ float sm[];
    float* Qs = sm;                    // 64 x PQ
    float* Ks = sm + 64 * PQ;          // 64 x PQ
    float* Vs = Ks + 64 * PQ;          // 64 x PV
    float* Ps = Vs + 64 * PV;          // 64 x PQ

    const int bh  = blockIdx.x;
    const int b   = bh >> 4;
    const int h   = bh & 15;
    const int qi  = blockIdx.y;
    const int tid = threadIdx.x;
    const int lane = tid & 31;
    const int wid  = tid >> 5;
    const int g    = lane >> 2;
    const int tg   = lane & 3;

    const float* Qg = g_q + ((size_t)bh * T_ + qi * 64) * D_;
    const float* Kg = g_k + (size_t)bh * T_ * D_;
    const float* Vg = g_v + (size_t)bh * T_ * D_;

    // Load Q tile (64x64), rounded
    for (int i = tid; i < 1024; i += 128) {
        int r = i >> 4, c = (i & 15) << 2;
        float4 v = *(const float4*)&Qg[r * D_ + c];
        Qs[r * PQ + c + 0] = tf32_round(v.x);
        Qs[r * PQ + c + 1] = tf32_round(v.y);
        Qs[r * PQ + c + 2] = tf32_round(v.z);
        Qs[r * PQ + c + 3] = tf32_round(v.w);
    }

    // ldmatrix lane bases
    const int qrow = wid * 16 + (lane & 7) + 8 * ((lane >> 3) & 1);
    const int khq  = lane >> 4;
    const uint32_t qbase = smem_u32(Qs) + qrow * (PQ * 4);
    const uint32_t pbase = smem_u32(Ps) + qrow * (PQ * 4);
    const int krow_l = (lane & 7) + 8 * (lane >> 4);    // + p*16
    const int khb    = (lane >> 3) & 1;
    const uint32_t kbase = smem_u32(Ks) + krow_l * (PQ * 4);

    float O[8][4];
#pragma unroll
    for (int ni = 0; ni < 8; ni++)
#pragma unroll
        for (int r = 0; r < 4; r++) O[ni][r] = 0.0f;
    float mrow0 = -1e30f, mrow1 = -1e30f;
    float lrow0 = 0.0f,   lrow1 = 0.0f;

    const int rloc = wid * 16 + g;
    const float scale = 0.125f;

    for (int j = 0; j <= qi; j++) {
        // Load K,V tiles (64x64 each)
        for (int i = tid; i < 1024; i += 128) {
            int r = i >> 4, c = (i & 15) << 2;
            float4 kv = *(const float4*)&Kg[((size_t)j * 64 + r) * D_ + c];
            Ks[r * PQ + c + 0] = tf32_round(kv.x);
            Ks[r * PQ + c + 1] = tf32_round(kv.y);
            Ks[r * PQ + c + 2] = tf32_round(kv.z);
            Ks[r * PQ + c + 3] = tf32_round(kv.w);
            float4 vv = *(const float4*)&Vg[((size_t)j * 64 + r) * D_ + c];
            Vs[r * PV + c + 0] = tf32_round(vv.x);
            Vs[r * PV + c + 1] = tf32_round(vv.y);
            Vs[r * PV + c + 2] = tf32_round(vv.z);
            Vs[r * PV + c + 3] = tf32_round(vv.w);
        }
        __syncthreads();

        // S = Q K^T
        float sfr[8][4];
#pragma unroll
        for (int ni = 0; ni < 8; ni++)
#pragma unroll
            for (int r = 0; r < 4; r++) sfr[ni][r] = 0.0f;

#pragma unroll
        for (int kk = 0; kk < 8; kk++) {
            uint32_t af[4];
            ldsm_x4(af, qbase + (((kk << 1) | khq) << 4));
            uint32_t bf[8][2];
#pragma unroll
            for (int p = 0; p < 4; p++) {
                uint32_t d[4];
                ldsm_x4(d, kbase + p * 16 * (PQ * 4) + (((kk << 1) | khb) << 4));
                bf[2 * p][0] = d[0]; bf[2 * p][1] = d[1];
                bf[2 * p + 1][0] = d[2]; bf[2 * p + 1][1] = d[3];
            }
#pragma unroll
            for (int ni = 0; ni < 8; ni++)
                mma_tf32(sfr[ni], af, bf[ni], sfr[ni]);
        }

        // Scale + causal mask (diagonal tile only)
        const bool diag = (j == qi);
        const int rowg0 = qi * 64 + rloc;
        const int rowg1 = rowg0 + 8;
#pragma unroll
        for (int ni = 0; ni < 8; ni++) {
#pragma unroll
            for (int r = 0; r < 4; r++) {
                float s = sfr[ni][r] * scale;
                if (diag) {
                    int colg = j * 64 + ni * 8 + tg * 2 + (r & 1);
                    int rowg = (r >> 1) ? rowg1 : rowg0;
                    if (colg > rowg) s = -1e30f;
                }
                sfr[ni][r] = s;
            }
        }

        // Online softmax (two rows per thread)
        float mx0 = -1e30f, mx1 = -1e30f;
#pragma unroll
        for (int ni = 0; ni < 8; ni++) {
            mx0 = fmaxf(mx0, fmaxf(sfr[ni][0], sfr[ni][1]));
            mx1 = fmaxf(mx1, fmaxf(sfr[ni][2], sfr[ni][3]));
        }
        mx0 = fmaxf(mx0, __shfl_xor_sync(0xffffffffu, mx0, 1));
        mx0 = fmaxf(mx0, __shfl_xor_sync(0xffffffffu, mx0, 2));
        mx1 = fmaxf(mx1, __shfl_xor_sync(0xffffffffu, mx1, 1));
        mx1 = fmaxf(mx1, __shfl_xor_sync(0xffffffffu, mx1, 2));

        float mn0 = fmaxf(mrow0, mx0);
        float mn1 = fmaxf(mrow1, mx1);
        float a0 = __expf(mrow0 - mn0);
        float a1 = __expf(mrow1 - mn1);

        float rs0 = 0.0f, rs1 = 0.0f;
#pragma unroll
        for (int ni = 0; ni < 8; ni++) {
            float p0 = __expf(sfr[ni][0] - mn0); sfr[ni][0] = p0; rs0 += p0;
            float p1 = __expf(sfr[ni][1] - mn0); sfr[ni][1] = p1; rs0 += p1;
            float p2 = __expf(sfr[ni][2] - mn1); sfr[ni][2] = p2; rs1 += p2;
            float p3 = __expf(sfr[ni][3] - mn1); sfr[ni][3] = p3; rs1 += p3;
        }
        rs0 += __shfl_xor_sync(0xffffffffu, rs0, 1);
        rs0 += __shfl_xor_sync(0xffffffffu, rs0, 2);
        rs1 += __shfl_xor_sync(0xffffffffu, rs1, 1);
        rs1 += __shfl_xor_sync(0xffffffffu, rs1, 2);

        lrow0 = lrow0 * a0 + rs0;
        lrow1 = lrow1 * a1 + rs1;
        mrow0 = mn0;
        mrow1 = mn1;

#pragma unroll
        for (int ni = 0; ni < 8; ni++) {
            O[ni][0] *= a0; O[ni][1] *= a0;
            O[ni][2] *= a1; O[ni][3] *= a1;
        }

        // P to smem (warp-private 16-row slab)
#pragma unroll
        for (int ni = 0; ni < 8; ni++) {
            int c = ni * 8 + tg * 2;
            Ps[(rloc    ) * PQ + c    ] = tf32_round(sfr[ni][0]);
            Ps[(rloc    ) * PQ + c + 1] = tf32_round(sfr[ni][1]);
            Ps[(rloc + 8) * PQ + c    ] = tf32_round(sfr[ni][2]);
            Ps[(rloc + 8) * PQ + c + 1] = tf32_round(sfr[ni][3]);
        }
        __syncwarp();

        // O += P @ V
#pragma unroll
        for (int kk = 0; kk < 8; kk++) {
            uint32_t af[4];
            ldsm_x4(af, pbase + (((kk << 1) | khq) << 4));
#pragma unroll
            for (int ni = 0; ni < 8; ni++) {
                uint32_t bf[2];
                bf[0] = __float_as_uint(Vs[(kk * 8 + tg    ) * PV + ni * 8 + g]);
                bf[1] = __float_as_uint(Vs[(kk * 8 + tg + 4) * PV + ni * 8 + g]);
                mma_tf32(O[ni], af, bf, O[ni]);
            }
        }
        __syncthreads();
    }

    // Epilogue: O /= l, tf32-round (out-proj consumes raw), write [B,T,H,D]
    float il0 = 1.0f / lrow0;
    float il1 = 1.0f / lrow1;
    int t0 = qi * 64 + rloc;
#pragma unroll
    for (int ni = 0; ni < 8; ni++) {
        int d = ni * 8 + tg * 2;
        size_t base0 = ((size_t)(b * T_ + t0    ) * H_ + h) * D_ + d;
        size_t base1 = ((size_t)(b * T_ + t0 + 8) * H_ + h) * D_ + d;
        float2 v0 = make_float2(tf32_round(O[ni][0] * il0), tf32_round(O[ni][1] * il0));
        float2 v1 = make_float2(tf32_round(O[ni][2] * il1), tf32_round(O[ni][3] * il1));
        *(float2*)&g_y[base0] = v0;
        *(float2*)&g_y[base1] = v1;
    }
}

// ---------------------------------------------------------------------------
// Launch
// ---------------------------------------------------------------------------
extern "C" void kernel_launch(void* const* d_in, const int* in_sizes, int n_in,
                              void* d_out, int out_size)
{
    const float* x     = (const float*)d_in[0];
    const float* Wqkv  = (const float*)d_in[1];
    const float* bqkv  = (const float*)d_in[2];
    const float* Wout  = (const float*)d_in[3];
    const float* bout  = (const float*)d_in[4];
    float* out = (float*)d_out;

    float *xr = nullptr, *wqkvT = nullptr, *woutT = nullptr, *yptr = nullptr;
    cudaGetSymbolAddress((void**)&xr, g_x);
    cudaGetSymbolAddress((void**)&wqkvT, g_wqkvT);
    cudaGetSymbolAddress((void**)&woutT, g_woutT);
    cudaGetSymbolAddress((void**)&yptr, g_y);

    cudaFuncSetAttribute(gemm_tf32<0>,
                         cudaFuncAttributeMaxDynamicSharedMemorySize, GEMM_SMEM);
    cudaFuncSetAttribute(gemm_tf32<1>,
                         cudaFuncAttributeMaxDynamicSharedMemorySize, GEMM_SMEM);
    cudaFuncSetAttribute(attn_kernel,
                         cudaFuncAttributeMaxDynamicSharedMemorySize, ATTN_SMEM);

    // 0) prep: round x; transpose+round W matrices (K-major B operands)
    round_copy<<<(B_ * T_ * C_ / 4 + 255) / 256, 256>>>(x, xr, B_ * T_ * C_ / 4);
    transpose_round<<<dim3(3 * C_ / 32, C_ / 32), dim3(32, 8)>>>(Wqkv, wqkvT, C_, 3 * C_);
    transpose_round<<<dim3(C_ / 32, C_ / 32), dim3(32, 8)>>>(Wout, woutT, C_, C_);

    // 1) QKV projection -> scatter q/k/v [B,H,T,D]
    gemm_tf32<0><<<dim3(3 * C_ / 128, B_ * T_ / 128), 256, GEMM_SMEM>>>(
        xr, wqkvT, bqkv, nullptr, 3 * C_);

    // 2) Causal flash attention -> g_y [B,T,C] (rounded)
    attn_kernel<<<dim3(BH_, T_ / 64), 128, ATTN_SMEM>>>();

    // 3) Output projection -> out
    gemm_tf32<1><<<dim3(C_ / 128, B_ * T_ / 128), 256, GEMM_SMEM>>>(
        yptr, woutT, bout, out, C_);
}

// round 5
// speedup vs baseline: 1.8409x; 1.1097x over previous
#include <cuda_runtime.h>
#include <cstdint>
#include <math.h>

// Problem constants
#define B_ 4
#define T_ 2048
#define C_ 1024
#define H_ 16
#define D_ 64
#define BH_ (B_ * H_)

// Scratch (device globals -- no allocation allowed)
__device__ float g_q[BH_ * T_ * D_];    // [B,H,T,D], tf32-rounded
__device__ float g_k[BH_ * T_ * D_];    // [B,H,T,D], tf32-rounded
__device__ float g_vt[BH_ * D_ * T_];   // [B,H,D,T], tf32-rounded (V transposed)
__device__ float g_y[B_ * T_ * C_];     // [B,T,C], tf32-rounded by attn epilogue
__device__ float g_x[B_ * T_ * C_];     // tf32-rounded x
__device__ float g_wqkvT[3 * C_ * C_];  // [3C, C] = W_qkv^T, tf32-rounded
__device__ float g_woutT[C_ * C_];      // [C, C]  = W_out^T, tf32-rounded

// ---------------------------------------------------------------------------
// Helpers
// ---------------------------------------------------------------------------
__device__ __forceinline__ float tf32_round(float x) {
    uint32_t u;
    asm("cvt.rna.tf32.f32 %0, %1;" : "=r"(u) : "f"(x));
    return __uint_as_float(u);
}

__device__ __forceinline__ uint32_t smem_u32(const void* p) {
    return (uint32_t)__cvta_generic_to_shared(p);
}

__device__ __forceinline__ void mma_tf32(float d[4], const uint32_t a[4],
                                         const uint32_t b[2], const float c[4]) {
    asm volatile(
        "mma.sync.aligned.m16n8k8.row.col.f32.tf32.tf32.f32 "
        "{%0,%1,%2,%3},{%4,%5,%6,%7},{%8,%9},{%10,%11,%12,%13};"
        : "=f"(d[0]), "=f"(d[1]), "=f"(d[2]), "=f"(d[3])
        : "r"(a[0]), "r"(a[1]), "r"(a[2]), "r"(a[3]),
          "r"(b[0]), "r"(b[1]),
          "f"(c[0]), "f"(c[1]), "f"(c[2]), "f"(c[3]));
}

__device__ __forceinline__ void ldsm_x4(uint32_t d[4], uint32_t saddr) {
    asm volatile(
        "ldmatrix.sync.aligned.m8n8.x4.shared.b16 {%0,%1,%2,%3}, [%4];"
        : "=r"(d[0]), "=r"(d[1]), "=r"(d[2]), "=r"(d[3]) : "r"(saddr));
}

__device__ __forceinline__ void cp_async16(uint32_t dst, const void* src) {
    asm volatile("cp.async.cg.shared.global [%0], [%1], 16;"
                 :: "r"(dst), "l"(src) : "memory");
}
__device__ __forceinline__ void cp_commit() {
    asm volatile("cp.async.commit_group;" ::: "memory");
}
template <int N>
__device__ __forceinline__ void cp_wait() {
    asm volatile("cp.async.wait_group %0;" :: "n"(N) : "memory");
}

// ---------------------------------------------------------------------------
// Prep kernels: tf32-round x; transpose+round W matrices
// ---------------------------------------------------------------------------
__global__ void round_copy(const float* __restrict__ in, float* __restrict__ out, int n4) {
    int i = blockIdx.x * blockDim.x + threadIdx.x;
    if (i < n4) {
        float4 v = ((const float4*)in)[i];
        v.x = tf32_round(v.x); v.y = tf32_round(v.y);
        v.z = tf32_round(v.z); v.w = tf32_round(v.w);
        ((float4*)out)[i] = v;
    }
}

__global__ void transpose_round(const float* __restrict__ in, float* __restrict__ out,
                                int R, int Ccols) {
    __shared__ float t[32][33];
    int bx = blockIdx.x * 32;
    int by = blockIdx.y * 32;
    int x = threadIdx.x, y = threadIdx.y;
#pragma unroll
    for (int j = 0; j < 32; j += 8)
        t[y + j][x] = in[(size_t)(by + y + j) * Ccols + bx + x];
    __syncthreads();
#pragma unroll
    for (int j = 0; j < 32; j += 8)
        out[(size_t)(bx + y + j) * R + by + x] = tf32_round(t[x][y + j]);
}

// ---------------------------------------------------------------------------
// TF32 GEMM: C[M, N] = A[M, 1024] @ Bt[N, 1024]^T + bias
// BM=128 BN=128 BK=32, 256 threads, cp.async 3-stage, ldmatrix both operands.
// MODE 0: tf32-round and scatter into g_q/g_k/g_vt. MODE 1: row-major + bias.
// ---------------------------------------------------------------------------
#define GKT 32
#define STAGE_B 16384
#define GEMM_SMEM (6 * STAGE_B)

template <int MODE>
__global__ __launch_bounds__(256, 2) void gemm_tf32(
    const float* __restrict__ Ag, const float* __restrict__ Bg,
    const float* __restrict__ bias, float* __restrict__ Cout, int N)
{
    extern __shared__ char smem[];
    const uint32_t sA = smem_u32(smem);
    const uint32_t sB = sA + 3 * STAGE_B;

    const int tid  = threadIdx.x;
    const int lane = tid & 31;
    const int wid  = tid >> 5;
    const int wr   = (wid >> 2) * 64;
    const int wc   = (wid & 3) * 32;
    const int m0   = blockIdx.y * 128;
    const int n0   = blockIdx.x * 128;

    const int lr = tid >> 3;
    const int lg = tid & 7;

    auto issue = [&](int kt) {
        const int s = kt % 3;
#pragma unroll
        for (int i = 0; i < 4; i++) {
            int r = lr + i * 32;
            uint32_t off = r * 128 + ((lg ^ (r & 7)) << 4);
            cp_async16(sA + s * STAGE_B + off,
                       Ag + (size_t)(m0 + r) * 1024 + kt * 32 + lg * 4);
            cp_async16(sB + s * STAGE_B + off,
                       Bg + (size_t)(n0 + r) * 1024 + kt * 32 + lg * 4);
        }
        cp_commit();
    };

    const int arow = wr + (lane & 7) + 8 * ((lane >> 3) & 1);
    const int kha  = lane >> 4;
    const int brow0 = wc + (lane & 7) + 8 * (lane >> 4);
    const int khb  = (lane >> 3) & 1;

    float acc[4][4][4];
#pragma unroll
    for (int mi = 0; mi < 4; mi++)
#pragma unroll
        for (int ni = 0; ni < 4; ni++)
#pragma unroll
            for (int r = 0; r < 4; r++) acc[mi][ni][r] = 0.0f;

    issue(0);
    issue(1);

    for (int kt = 0; kt < GKT; kt++) {
        if (kt + 1 < GKT) cp_wait<1>(); else cp_wait<0>();
        __syncthreads();
        if (kt + 2 < GKT) issue(kt + 2);

        const int s = kt % 3;
        const uint32_t aS = sA + s * STAGE_B;
        const uint32_t bS = sB + s * STAGE_B;

#pragma unroll
        for (int kk = 0; kk < 4; kk++) {
            uint32_t af[4][4];
#pragma unroll
            for (int mi = 0; mi < 4; mi++) {
                int r = arow + mi * 16;
                uint32_t addr = aS + r * 128 +
                                ((((kk << 1) | kha) ^ (r & 7)) << 4);
                ldsm_x4(af[mi], addr);
            }
            uint32_t bf[4][2];
#pragma unroll
            for (int p = 0; p < 2; p++) {
                int r = brow0 + p * 16;
                uint32_t addr = bS + r * 128 +
                                ((((kk << 1) | khb) ^ (r & 7)) << 4);
                uint32_t d[4];
                ldsm_x4(d, addr);
                bf[2 * p][0] = d[0]; bf[2 * p][1] = d[1];
                bf[2 * p + 1][0] = d[2]; bf[2 * p + 1][1] = d[3];
            }
#pragma unroll
            for (int mi = 0; mi < 4; mi++)
#pragma unroll
                for (int ni = 0; ni < 4; ni++)
                    mma_tf32(acc[mi][ni], af[mi], bf[ni], acc[mi][ni]);
        }
        __syncthreads();
    }

    // Epilogue
    const int g  = lane >> 2;
    const int tg = lane & 3;
#pragma unroll
    for (int mi = 0; mi < 4; mi++) {
#pragma unroll
        for (int ni = 0; ni < 4; ni++) {
#pragma unroll
            for (int r = 0; r < 4; r++) {
                int row = m0 + wr + mi * 16 + g + ((r >> 1) ? 8 : 0);
                int col = n0 + wc + ni * 8 + tg * 2 + (r & 1);
                float v = acc[mi][ni][r] + __ldg(&bias[col]);
                if (MODE == 0) {
                    v = tf32_round(v);             // pre-round q/k/v for attention
                    int b = row >> 11;
                    int t = row & (T_ - 1);
                    int which = col >> 10;
                    int rr = col & (C_ - 1);
                    int h = rr >> 6;
                    int d = rr & 63;
                    size_t bhh = (size_t)(b * H_ + h);
                    if (which == 2) {
                        g_vt[(bhh * D_ + d) * T_ + t] = v;          // transposed V
                    } else {
                        float* dst = (which == 0) ? g_q : g_k;
                        dst[(bhh * T_ + t) * D_ + d] = v;
                    }
                } else {
                    Cout[(size_t)row * N + col] = v;
                }
            }
        }
    }
}

// ---------------------------------------------------------------------------
// Flash attention (causal), BQ=64 BKV=64, 128 threads (4 warps).
// All tiles 64 rows x 256B, swizzled; Q/K/P/Vt fragments all via ldmatrix.
// K + Vt double-buffered via cp.async (inputs pre-rounded by GEMM epilogue).
// ---------------------------------------------------------------------------
#define STG 16384
#define ATTN_SMEM (6 * STG)   // Q | K x2 | Vt x2 | P  = 98304 bytes

__global__ __launch_bounds__(128, 2) void attn_kernel()
{
    extern __shared__ char smc[];
    const uint32_t sQ = smem_u32(smc);
    const uint32_t sK = sQ + STG;        // + s*STG
    const uint32_t sV = sQ + 3 * STG;    // + s*STG
    const uint32_t sP = sQ + 5 * STG;

    const int bh  = blockIdx.x;
    const int b   = bh >> 4;
    const int h   = bh & 15;
    const int qi  = blockIdx.y;
    const int tid = threadIdx.x;
    const int lane = tid & 31;
    const int wid  = tid >> 5;
    const int g    = lane >> 2;
    const int tg   = lane & 3;

    const float* Qg  = g_q  + ((size_t)bh * T_ + qi * 64) * D_;
    const float* Kg  = g_k  + (size_t)bh * T_ * D_;
    const float* Vtg = g_vt + (size_t)bh * D_ * T_;

    // Q tile -> swizzled smem (already rounded)
#pragma unroll
    for (int it = 0; it < 8; it++) {
        int i = tid + it * 128;
        int r = i >> 4, gg = i & 15;
        float4 v = *(const float4*)&Qg[r * 64 + gg * 4];
        *(float4*)(smc + r * 256 + ((gg ^ (r & 7)) << 4)) = v;
    }

    auto issue = [&](int j, int s) {
#pragma unroll
        for (int it = 0; it < 8; it++) {
            int i = tid + it * 128;
            int r = i >> 4, gg = i & 15;
            uint32_t sw = r * 256 + ((gg ^ (r & 7)) << 4);
            cp_async16(sK + s * STG + sw, Kg  + ((size_t)j * 64 + r) * 64 + gg * 4);
            cp_async16(sV + s * STG + sw, Vtg + (size_t)r * T_ + j * 64 + gg * 4);
        }
        cp_commit();
    };

    issue(0, 0);
    if (qi >= 1) issue(1, 1);

    // fragment lane constants
    const int qrow = wid * 16 + (lane & 7) + 8 * ((lane >> 3) & 1);
    const int khq  = lane >> 4;
    const int qxk  = qrow & 7;
    const uint32_t qbase = sQ + qrow * 256;
    const uint32_t pbase = sP + qrow * 256;
    const int brow = (lane & 7) + 8 * (lane >> 4);    // + p*16
    const int khb  = (lane >> 3) & 1;

    float O[8][4];
#pragma unroll
    for (int ni = 0; ni < 8; ni++)
#pragma unroll
        for (int r = 0; r < 4; r++) O[ni][r] = 0.0f;
    float mrow0 = -1e30f, mrow1 = -1e30f;
    float lrow0 = 0.0f,   lrow1 = 0.0f;

    const int rloc = wid * 16 + g;
    const float scale = 0.125f;

    for (int j = 0; j <= qi; j++) {
        const int s = j & 1;
        if (j < qi) cp_wait<1>(); else cp_wait<0>();
        __syncthreads();

        const uint32_t kS = sK + s * STG;
        const uint32_t vS = sV + s * STG;

        // S = Q K^T
        float sfr[8][4];
#pragma unroll
        for (int ni = 0; ni < 8; ni++)
#pragma unroll
            for (int r = 0; r < 4; r++) sfr[ni][r] = 0.0f;

#pragma unroll
        for (int kk = 0; kk < 8; kk++) {
            uint32_t af[4];
            ldsm_x4(af, qbase + ((((kk << 1) | khq) ^ qxk) << 4));
            uint32_t bf[8][2];
#pragma unroll
            for (int p = 0; p < 4; p++) {
                int r = brow + p * 16;
                uint32_t d[4];
                ldsm_x4(d, kS + r * 256 + ((((kk << 1) | khb) ^ (r & 7)) << 4));
                bf[2 * p][0] = d[0]; bf[2 * p][1] = d[1];
                bf[2 * p + 1][0] = d[2]; bf[2 * p + 1][1] = d[3];
            }
#pragma unroll
            for (int ni = 0; ni < 8; ni++)
                mma_tf32(sfr[ni], af, bf[ni], sfr[ni]);
        }

        // Scale + causal mask (diagonal tile only)
        const bool diag = (j == qi);
        const int rowg0 = qi * 64 + rloc;
        const int rowg1 = rowg0 + 8;
#pragma unroll
        for (int ni = 0; ni < 8; ni++) {
#pragma unroll
            for (int r = 0; r < 4; r++) {
                float sv = sfr[ni][r] * scale;
                if (diag) {
                    int colg = j * 64 + ni * 8 + tg * 2 + (r & 1);
                    int rowg = (r >> 1) ? rowg1 : rowg0;
                    if (colg > rowg) sv = -1e30f;
                }
                sfr[ni][r] = sv;
            }
        }

        // Online softmax (two rows per thread)
        float mx0 = -1e30f, mx1 = -1e30f;
#pragma unroll
        for (int ni = 0; ni < 8; ni++) {
            mx0 = fmaxf(mx0, fmaxf(sfr[ni][0], sfr[ni][1]));
            mx1 = fmaxf(mx1, fmaxf(sfr[ni][2], sfr[ni][3]));
        }
        mx0 = fmaxf(mx0, __shfl_xor_sync(0xffffffffu, mx0, 1));
        mx0 = fmaxf(mx0, __shfl_xor_sync(0xffffffffu, mx0, 2));
        mx1 = fmaxf(mx1, __shfl_xor_sync(0xffffffffu, mx1, 1));
        mx1 = fmaxf(mx1, __shfl_xor_sync(0xffffffffu, mx1, 2));

        float mn0 = fmaxf(mrow0, mx0);
        float mn1 = fmaxf(mrow1, mx1);
        float a0 = __expf(mrow0 - mn0);
        float a1 = __expf(mrow1 - mn1);

        float rs0 = 0.0f, rs1 = 0.0f;
#pragma unroll
        for (int ni = 0; ni < 8; ni++) {
            float p0 = __expf(sfr[ni][0] - mn0); sfr[ni][0] = p0; rs0 += p0;
            float p1 = __expf(sfr[ni][1] - mn0); sfr[ni][1] = p1; rs0 += p1;
            float p2 = __expf(sfr[ni][2] - mn1); sfr[ni][2] = p2; rs1 += p2;
            float p3 = __expf(sfr[ni][3] - mn1); sfr[ni][3] = p3; rs1 += p3;
        }
        rs0 += __shfl_xor_sync(0xffffffffu, rs0, 1);
        rs0 += __shfl_xor_sync(0xffffffffu, rs0, 2);
        rs1 += __shfl_xor_sync(0xffffffffu, rs1, 1);
        rs1 += __shfl_xor_sync(0xffffffffu, rs1, 2);

        lrow0 = lrow0 * a0 + rs0;
        lrow1 = lrow1 * a1 + rs1;
        mrow0 = mn0;
        mrow1 = mn1;

#pragma unroll
        for (int ni = 0; ni < 8; ni++) {
            O[ni][0] *= a0; O[ni][1] *= a0;
            O[ni][2] *= a1; O[ni][3] *= a1;
        }

        // P -> swizzled smem (rounded), warp-private rows
        {
            const int xk = rloc & 7;
            const int off8 = (tg & 1) * 8;
#pragma unroll
            for (int ni = 0; ni < 8; ni++) {
                int gp = ni * 2 + (tg >> 1);
                uint32_t o0 = 5 * STG + rloc * 256 + ((gp ^ xk) << 4) + off8;
                uint32_t o1 = o0 + 8 * 256;
                *(float2*)(smc + o0) =
                    make_float2(tf32_round(sfr[ni][0]), tf32_round(sfr[ni][1]));
                *(float2*)(smc + o1) =
                    make_float2(tf32_round(sfr[ni][2]), tf32_round(sfr[ni][3]));
            }
        }
        __syncwarp();

        // O += P @ V   (Vt fragments via ldmatrix)
#pragma unroll
        for (int kk = 0; kk < 8; kk++) {
            uint32_t af[4];
            ldsm_x4(af, pbase + ((((kk << 1) | khq) ^ qxk) << 4));
            uint32_t bf[8][2];
#pragma unroll
            for (int p = 0; p < 4; p++) {
                int r = brow + p * 16;
                uint32_t d[4];
                ldsm_x4(d, vS + r * 256 + ((((kk << 1) | khb) ^ (r & 7)) << 4));
                bf[2 * p][0] = d[0]; bf[2 * p][1] = d[1];
                bf[2 * p + 1][0] = d[2]; bf[2 * p + 1][1] = d[3];
            }
#pragma unroll
            for (int ni = 0; ni < 8; ni++)
                mma_tf32(O[ni], af, bf[ni], O[ni]);
        }
        __syncthreads();
        if (j + 2 <= qi) issue(j + 2, s);
    }

    // Epilogue: O /= l, tf32-round (out-proj consumes), write [B,T,H,D]
    float il0 = 1.0f / lrow0;
    float il1 = 1.0f / lrow1;
    int t0 = qi * 64 + rloc;
#pragma unroll
    for (int ni = 0; ni < 8; ni++) {
        int d = ni * 8 + tg * 2;
        size_t base0 = ((size_t)(b * T_ + t0    ) * H_ + h) * D_ + d;
        size_t base1 = ((size_t)(b * T_ + t0 + 8) * H_ + h) * D_ + d;
        float2 v0 = make_float2(tf32_round(O[ni][0] * il0), tf32_round(O[ni][1] * il0));
        float2 v1 = make_float2(tf32_round(O[ni][2] * il1), tf32_round(O[ni][3] * il1));
        *(float2*)&g_y[base0] = v0;
        *(float2*)&g_y[base1] = v1;
    }
}

// ---------------------------------------------------------------------------
// Launch
// ---------------------------------------------------------------------------
extern "C" void kernel_launch(void* const* d_in, const int* in_sizes, int n_in,
                              void* d_out, int out_size)
{
    const float* x     = (const float*)d_in[0];
    const float* Wqkv  = (const float*)d_in[1];
    const float* bqkv  = (const float*)d_in[2];
    const float* Wout  = (const float*)d_in[3];
    const float* bout  = (const float*)d_in[4];
    float* out = (float*)d_out;

    float *xr = nullptr, *wqkvT = nullptr, *woutT = nullptr, *yptr = nullptr;
    cudaGetSymbolAddress((void**)&xr, g_x);
    cudaGetSymbolAddress((void**)&wqkvT, g_wqkvT);
    cudaGetSymbolAddress((void**)&woutT, g_woutT);
    cudaGetSymbolAddress((void**)&yptr, g_y);

    cudaFuncSetAttribute(gemm_tf32<0>,
                         cudaFuncAttributeMaxDynamicSharedMemorySize, GEMM_SMEM);
    cudaFuncSetAttribute(gemm_tf32<1>,
                         cudaFuncAttributeMaxDynamicSharedMemorySize, GEMM_SMEM);
    cudaFuncSetAttribute(attn_kernel,
                         cudaFuncAttributeMaxDynamicSharedMemorySize, ATTN_SMEM);

    // 0) prep
    round_copy<<<(B_ * T_ * C_ / 4 + 255) / 256, 256>>>(x, xr, B_ * T_ * C_ / 4);
    transpose_round<<<dim3(3 * C_ / 32, C_ / 32), dim3(32, 8)>>>(Wqkv, wqkvT, C_, 3 * C_);
    transpose_round<<<dim3(C_ / 32, C_ / 32), dim3(32, 8)>>>(Wout, woutT, C_, C_);

    // 1) QKV projection -> rounded q/k (BHTD) + vt (BHDT)
    gemm_tf32<0><<<dim3(3 * C_ / 128, B_ * T_ / 128), 256, GEMM_SMEM>>>(
        xr, wqkvT, bqkv, nullptr, 3 * C_);

    // 2) Causal flash attention -> g_y (rounded)
    attn_kernel<<<dim3(BH_, T_ / 64), 128, ATTN_SMEM>>>();

    // 3) Output projection -> out
    gemm_tf32<1><<<dim3(C_ / 128, B_ * T_ / 128), 256, GEMM_SMEM>>>(
        yptr, woutT, bout, out, C_);
}

// round 6
// speedup vs baseline: 3.2293x; 1.7542x over previous
#include <cuda_runtime.h>
#include <cuda_fp16.h>
#include <cstdint>
#include <math.h>

// Problem constants
#define B_ 4
#define T_ 2048
#define C_ 1024
#define H_ 16
#define D_ 64
#define BH_ (B_ * H_)

// Scratch (device globals -- no allocation allowed)
__device__ __half g_q16[BH_ * T_ * D_];     // [B,H,T,D]
__device__ __half g_k16[BH_ * T_ * D_];     // [B,H,T,D]
__device__ __half g_vt16[BH_ * D_ * T_];    // [B,H,D,T]  (V transposed)
__device__ __half g_y16[B_ * T_ * C_];      // [B,T,C]
__device__ __half g_x16[B_ * T_ * C_];      // x -> half
__device__ __half g_wqkvT16[3 * C_ * C_];   // [3C, C] = W_qkv^T
__device__ __half g_woutT16[C_ * C_];       // [C, C]  = W_out^T

// ---------------------------------------------------------------------------
// Helpers
// ---------------------------------------------------------------------------
__device__ __forceinline__ uint32_t smem_u32(const void* p) {
    return (uint32_t)__cvta_generic_to_shared(p);
}

__device__ __forceinline__ float ex2f(float x) {
    float y;
    asm("ex2.approx.f32 %0, %1;" : "=f"(y) : "f"(x));
    return y;
}

__device__ __forceinline__ void mma_f16(float d[4], const uint32_t a[4],
                                        const uint32_t b[2], const float c[4]) {
    asm volatile(
        "mma.sync.aligned.m16n8k16.row.col.f32.f16.f16.f32 "
        "{%0,%1,%2,%3},{%4,%5,%6,%7},{%8,%9},{%10,%11,%12,%13};"
        : "=f"(d[0]), "=f"(d[1]), "=f"(d[2]), "=f"(d[3])
        : "r"(a[0]), "r"(a[1]), "r"(a[2]), "r"(a[3]),
          "r"(b[0]), "r"(b[1]),
          "f"(c[0]), "f"(c[1]), "f"(c[2]), "f"(c[3]));
}

__device__ __forceinline__ void ldsm_x4(uint32_t d[4], uint32_t saddr) {
    asm volatile(
        "ldmatrix.sync.aligned.m8n8.x4.shared.b16 {%0,%1,%2,%3}, [%4];"
        : "=r"(d[0]), "=r"(d[1]), "=r"(d[2]), "=r"(d[3]) : "r"(saddr));
}

__device__ __forceinline__ void cp_async16(uint32_t dst, const void* src) {
    asm volatile("cp.async.cg.shared.global [%0], [%1], 16;"
                 :: "r"(dst), "l"(src) : "memory");
}
__device__ __forceinline__ void cp_commit() {
    asm volatile("cp.async.commit_group;" ::: "memory");
}
template <int N>
__device__ __forceinline__ void cp_wait() {
    asm volatile("cp.async.wait_group %0;" :: "n"(N) : "memory");
}

// ---------------------------------------------------------------------------
// Prep kernels: fp32 -> fp16 copies / transposes
// ---------------------------------------------------------------------------
__global__ void to_half(const float* __restrict__ in, __half* __restrict__ out, int n4) {
    int i = blockIdx.x * blockDim.x + threadIdx.x;
    if (i < n4) {
        float4 v = ((const float4*)in)[i];
        __half2* o = (__half2*)(out + i * 4);
        o[0] = __floats2half2_rn(v.x, v.y);
        o[1] = __floats2half2_rn(v.z, v.w);
    }
}

// in: [R, Ccols] fp32 row-major -> out: [Ccols, R] half row-major
__global__ void transpose_half(const float* __restrict__ in, __half* __restrict__ out,
                               int R, int Ccols) {
    __shared__ float t[32][33];
    int bx = blockIdx.x * 32;
    int by = blockIdx.y * 32;
    int x = threadIdx.x, y = threadIdx.y;
#pragma unroll
    for (int j = 0; j < 32; j += 8)
        t[y + j][x] = in[(size_t)(by + y + j) * Ccols + bx + x];
    __syncthreads();
#pragma unroll
    for (int j = 0; j < 32; j += 8)
        out[(size_t)(bx + y + j) * R + by + x] = __float2half_rn(t[x][y + j]);
}

// ---------------------------------------------------------------------------
// FP16 GEMM: C[M, N] = A[M, 1024] @ Bt[N, 1024]^T + bias  (fp32 accumulate)
// BM=128 BN=128 BK=64 halves (128B swizzled rows), 256 threads (8 warps 2x4),
// warp tile 64x32. cp.async 3-stage, 1 sync/iter, ldmatrix both operands.
// MODE 0: convert to half + scatter q/k (BHTD) and vt (BHDT).
// MODE 1: fp32 row-major store + bias.
// ---------------------------------------------------------------------------
#define GKT 16                    // k-tiles (K=1024 / 64)
#define STAGE_B 16384             // 128 rows x 128B
#define GEMM_SMEM (6 * STAGE_B)   // 3 stages x (A+B) = 98304

template <int MODE>
__global__ __launch_bounds__(256, 2) void gemm_f16(
    const __half* __restrict__ Ag, const __half* __restrict__ Bg,
    const float* __restrict__ bias, float* __restrict__ Cout, int N)
{
    extern __shared__ char smem[];
    const uint32_t sA = smem_u32(smem);
    const uint32_t sB = sA + 3 * STAGE_B;

    const int tid  = threadIdx.x;
    const int lane = tid & 31;
    const int wid  = tid >> 5;
    const int wr   = (wid >> 2) * 64;
    const int wc   = (wid & 3) * 32;
    const int m0   = blockIdx.y * 128;
    const int n0   = blockIdx.x * 128;

    const int lr = tid >> 3;      // + i*32
    const int lg = tid & 7;       // 16B group (8 halves)

    auto issue = [&](int kt) {
        const int s = kt % 3;
#pragma unroll
        for (int i = 0; i < 4; i++) {
            int r = lr + i * 32;
            uint32_t off = r * 128 + ((lg ^ (r & 7)) << 4);
            cp_async16(sA + s * STAGE_B + off,
                       Ag + (size_t)(m0 + r) * 1024 + kt * 64 + lg * 8);
            cp_async16(sB + s * STAGE_B + off,
                       Bg + (size_t)(n0 + r) * 1024 + kt * 64 + lg * 8);
        }
        cp_commit();
    };

    // fragment lane mapping (verified layout from tf32 rounds; same for f16)
    const int arow  = wr + (lane & 7) + 8 * ((lane >> 3) & 1);
    const int kha   = lane >> 4;
    const int brow0 = wc + (lane & 7) + 8 * (lane >> 4);
    const int khb   = (lane >> 3) & 1;

    float acc[4][4][4];
#pragma unroll
    for (int mi = 0; mi < 4; mi++)
#pragma unroll
        for (int ni = 0; ni < 4; ni++)
#pragma unroll
            for (int r = 0; r < 4; r++) acc[mi][ni][r] = 0.0f;

    issue(0);
    issue(1);

    for (int kt = 0; kt < GKT; kt++) {
        if (kt + 1 < GKT) cp_wait<1>(); else cp_wait<0>();
        __syncthreads();
        if (kt + 2 < GKT) issue(kt + 2);

        const int s = kt % 3;
        const uint32_t aS = sA + s * STAGE_B;
        const uint32_t bS = sB + s * STAGE_B;

#pragma unroll
        for (int kk = 0; kk < 4; kk++) {      // 4 x k16 = 64 k-depth
            uint32_t af[4][4];
#pragma unroll
            for (int mi = 0; mi < 4; mi++) {
                int r = arow + mi * 16;
                uint32_t addr = aS + r * 128 +
                                ((((kk << 1) | kha) ^ (r & 7)) << 4);
                ldsm_x4(af[mi], addr);
            }
            uint32_t bf[4][2];
#pragma unroll
            for (int p = 0; p < 2; p++) {
                int r = brow0 + p * 16;
                uint32_t addr = bS + r * 128 +
                                ((((kk << 1) | khb) ^ (r & 7)) << 4);
                uint32_t d[4];
                ldsm_x4(d, addr);
                bf[2 * p][0] = d[0]; bf[2 * p][1] = d[1];
                bf[2 * p + 1][0] = d[2]; bf[2 * p + 1][1] = d[3];
            }
#pragma unroll
            for (int mi = 0; mi < 4; mi++)
#pragma unroll
                for (int ni = 0; ni < 4; ni++)
                    mma_f16(acc[mi][ni], af[mi], bf[ni], acc[mi][ni]);
        }
        // no trailing sync: next iter's top sync protects stage reuse
    }

    // Epilogue
    const int g  = lane >> 2;
    const int tg = lane & 3;
#pragma unroll
    for (int mi = 0; mi < 4; mi++) {
#pragma unroll
        for (int ni = 0; ni < 4; ni++) {
#pragma unroll
            for (int r = 0; r < 4; r++) {
                int row = m0 + wr + mi * 16 + g + ((r >> 1) ? 8 : 0);
                int col = n0 + wc + ni * 8 + tg * 2 + (r & 1);
                float v = acc[mi][ni][r] + __ldg(&bias[col]);
                if (MODE == 0) {
                    __half hv = __float2half_rn(v);
                    int b = row >> 11;
                    int t = row & (T_ - 1);
                    int which = col >> 10;
                    int rr = col & (C_ - 1);
                    int h = rr >> 6;
                    int d = rr & 63;
                    size_t bhh = (size_t)(b * H_ + h);
                    if (which == 2) {
                        g_vt16[(bhh * D_ + d) * T_ + t] = hv;
                    } else {
                        __half* dst = (which == 0) ? g_q16 : g_k16;
                        dst[(bhh * T_ + t) * D_ + d] = hv;
                    }
                } else {
                    Cout[(size_t)row * N + col] = v;
                }
            }
        }
    }
}

// ---------------------------------------------------------------------------
// Flash attention (causal), fp16 mma, BQ=64 BKV=64, 128 threads (4 warps).
// Tiles: 64 rows x 128B (64 halves), swizzled; all fragments via ldmatrix.
// K + Vt double-buffered via cp.async. Softmax fp32, base-2.
// ---------------------------------------------------------------------------
#define ATG 8192                         // one tile: 64 x 128B
#define AQ_OFF 0
#define AK_OFF ATG                       // + s*ATG   (2 stages)
#define AV_OFF (3 * ATG)                 // + s*ATG   (2 stages)
#define AP_OFF (5 * ATG)
#define ATTN_SMEM (6 * ATG)              // 49152 bytes

__global__ __launch_bounds__(128, 4) void attn_kernel()
{
    extern __shared__ char smc[];
    const uint32_t sQ = smem_u32(smc);

    const int bh  = blockIdx.x;
    const int b   = bh >> 4;
    const int h   = bh & 15;
    const int qi  = blockIdx.y;
    const int tid = threadIdx.x;
    const int lane = tid & 31;
    const int wid  = tid >> 5;
    const int g    = lane >> 2;
    const int tg   = lane & 3;

    const __half* Qg  = g_q16  + ((size_t)bh * T_ + qi * 64) * D_;
    const __half* Kg  = g_k16  + (size_t)bh * T_ * D_;
    const __half* Vtg = g_vt16 + (size_t)bh * D_ * T_;

    // Q tile -> swizzled smem
#pragma unroll
    for (int it = 0; it < 4; it++) {
        int i = tid + it * 128;
        int r = i >> 3, gg = i & 7;
        uint4 v = *(const uint4*)&Qg[r * 64 + gg * 8];
        *(uint4*)(smc + r * 128 + ((gg ^ (r & 7)) << 4)) = v;
    }

    auto issue = [&](int j, int s) {
#pragma unroll
        for (int it = 0; it < 4; it++) {
            int i = tid + it * 128;
            int r = i >> 3, gg = i & 7;
            uint32_t sw = r * 128 + ((gg ^ (r & 7)) << 4);
            cp_async16(sQ + AK_OFF + s * ATG + sw,
                       Kg + ((size_t)j * 64 + r) * 64 + gg * 8);
            cp_async16(sQ + AV_OFF + s * ATG + sw,
                       Vtg + (size_t)r * T_ + j * 64 + gg * 8);
        }
        cp_commit();
    };

    issue(0, 0);
    if (qi >= 1) issue(1, 1);

    // fragment lane constants
    const int qrow = wid * 16 + (lane & 7) + 8 * ((lane >> 3) & 1);
    const int khq  = lane >> 4;
    const int qxk  = qrow & 7;
    const uint32_t qbase = sQ + AQ_OFF + qrow * 128;
    const uint32_t pbase = sQ + AP_OFF + qrow * 128;
    const int brow = (lane & 7) + 8 * (lane >> 4);    // + p*16
    const int khb  = (lane >> 3) & 1;

    float O[8][4];
#pragma unroll
    for (int ni = 0; ni < 8; ni++)
#pragma unroll
        for (int r = 0; r < 4; r++) O[ni][r] = 0.0f;
    float mrow0 = -1e30f, mrow1 = -1e30f;
    float lrow0 = 0.0f,   lrow1 = 0.0f;

    const int rloc = wid * 16 + g;
    const float scale = 0.125f * 1.4426950408889634f;   // 1/sqrt(D) * log2(e)

    for (int j = 0; j <= qi; j++) {
        const int s = j & 1;
        if (j < qi) cp_wait<1>(); else cp_wait<0>();
        __syncthreads();

        const uint32_t kS = sQ + AK_OFF + s * ATG;
        const uint32_t vS = sQ + AV_OFF + s * ATG;

        // S = Q K^T  (fp32 accum)
        float sfr[8][4];
#pragma unroll
        for (int ni = 0; ni < 8; ni++)
#pragma unroll
            for (int r = 0; r < 4; r++) sfr[ni][r] = 0.0f;

#pragma unroll
        for (int kk = 0; kk < 4; kk++) {
            uint32_t af[4];
            ldsm_x4(af, qbase + ((((kk << 1) | khq) ^ qxk) << 4));
            uint32_t bf[8][2];
#pragma unroll
            for (int p = 0; p < 4; p++) {
                int r = brow + p * 16;
                uint32_t d[4];
                ldsm_x4(d, kS + r * 128 + ((((kk << 1) | khb) ^ (r & 7)) << 4));
                bf[2 * p][0] = d[0]; bf[2 * p][1] = d[1];
                bf[2 * p + 1][0] = d[2]; bf[2 * p + 1][1] = d[3];
            }
#pragma unroll
            for (int ni = 0; ni < 8; ni++)
                mma_f16(sfr[ni], af, bf[ni], sfr[ni]);
        }

        // Scale (base-2) + causal mask (diagonal tile only)
        const bool diag = (j == qi);
        const int rowg0 = qi * 64 + rloc;
        const int rowg1 = rowg0 + 8;
#pragma unroll
        for (int ni = 0; ni < 8; ni++) {
#pragma unroll
            for (int r = 0; r < 4; r++) {
                float sv = sfr[ni][r] * scale;
                if (diag) {
                    int colg = j * 64 + ni * 8 + tg * 2 + (r & 1);
                    int rowg = (r >> 1) ? rowg1 : rowg0;
                    if (colg > rowg) sv = -1e30f;
                }
                sfr[ni][r] = sv;
            }
        }

        // Online softmax (base-2; two rows per thread)
        float mx0 = -1e30f, mx1 = -1e30f;
#pragma unroll
        for (int ni = 0; ni < 8; ni++) {
            mx0 = fmaxf(mx0, fmaxf(sfr[ni][0], sfr[ni][1]));
            mx1 = fmaxf(mx1, fmaxf(sfr[ni][2], sfr[ni][3]));
        }
        mx0 = fmaxf(mx0, __shfl_xor_sync(0xffffffffu, mx0, 1));
        mx0 = fmaxf(mx0, __shfl_xor_sync(0xffffffffu, mx0, 2));
        mx1 = fmaxf(mx1, __shfl_xor_sync(0xffffffffu, mx1, 1));
        mx1 = fmaxf(mx1, __shfl_xor_sync(0xffffffffu, mx1, 2));

        float mn0 = fmaxf(mrow0, mx0);
        float mn1 = fmaxf(mrow1, mx1);
        float a0 = ex2f(mrow0 - mn0);
        float a1 = ex2f(mrow1 - mn1);

        float rs0 = 0.0f, rs1 = 0.0f;
#pragma unroll
        for (int ni = 0; ni < 8; ni++) {
            float p0 = ex2f(sfr[ni][0] - mn0); sfr[ni][0] = p0; rs0 += p0;
            float p1 = ex2f(sfr[ni][1] - mn0); sfr[ni][1] = p1; rs0 += p1;
            float p2 = ex2f(sfr[ni][2] - mn1); sfr[ni][2] = p2; rs1 += p2;
            float p3 = ex2f(sfr[ni][3] - mn1); sfr[ni][3] = p3; rs1 += p3;
        }
        rs0 += __shfl_xor_sync(0xffffffffu, rs0, 1);
        rs0 += __shfl_xor_sync(0xffffffffu, rs0, 2);
        rs1 += __shfl_xor_sync(0xffffffffu, rs1, 1);
        rs1 += __shfl_xor_sync(0xffffffffu, rs1, 2);

        lrow0 = lrow0 * a0 + rs0;
        lrow1 = lrow1 * a1 + rs1;
        mrow0 = mn0;
        mrow1 = mn1;

#pragma unroll
        for (int ni = 0; ni < 8; ni++) {
            O[ni][0] *= a0; O[ni][1] *= a0;
            O[ni][2] *= a1; O[ni][3] *= a1;
        }

        // P -> swizzled smem as half2 (warp-private rows)
        {
            const int xk = rloc & 7;
#pragma unroll
            for (int ni = 0; ni < 8; ni++) {
                uint32_t o0 = AP_OFF + rloc * 128 + ((ni ^ xk) << 4) + tg * 4;
                *(__half2*)(smc + o0) = __floats2half2_rn(sfr[ni][0], sfr[ni][1]);
                *(__half2*)(smc + o0 + 8 * 128) = __floats2half2_rn(sfr[ni][2], sfr[ni][3]);
            }
        }
        __syncwarp();

        // O += P @ V   (Vt fragments via ldmatrix)
#pragma unroll
        for (int kk = 0; kk < 4; kk++) {
            uint32_t af[4];
            ldsm_x4(af, pbase + ((((kk << 1) | khq) ^ qxk) << 4));
            uint32_t bf[8][2];
#pragma unroll
            for (int p = 0; p < 4; p++) {
                int r = brow + p * 16;
                uint32_t d[4];
                ldsm_x4(d, vS + r * 128 + ((((kk << 1) | khb) ^ (r & 7)) << 4));
                bf[2 * p][0] = d[0]; bf[2 * p][1] = d[1];
                bf[2 * p + 1][0] = d[2]; bf[2 * p + 1][1] = d[3];
            }
#pragma unroll
            for (int ni = 0; ni < 8; ni++)
                mma_f16(O[ni], af, bf[ni], O[ni]);
        }
        __syncthreads();
        if (j + 2 <= qi) issue(j + 2, s);
    }

    // Epilogue: O /= l, convert to half, write [B,T,H,D]
    float il0 = 1.0f / lrow0;
    float il1 = 1.0f / lrow1;
    int t0 = qi * 64 + rloc;
#pragma unroll
    for (int ni = 0; ni < 8; ni++) {
        int d = ni * 8 + tg * 2;
        size_t base0 = ((size_t)(b * T_ + t0    ) * H_ + h) * D_ + d;
        size_t base1 = ((size_t)(b * T_ + t0 + 8) * H_ + h) * D_ + d;
        *(__half2*)&g_y16[base0] = __floats2half2_rn(O[ni][0] * il0, O[ni][1] * il0);
        *(__half2*)&g_y16[base1] = __floats2half2_rn(O[ni][2] * il1, O[ni][3] * il1);
    }
}

// ---------------------------------------------------------------------------
// Launch
// ---------------------------------------------------------------------------
extern "C" void kernel_launch(void* const* d_in, const int* in_sizes, int n_in,
                              void* d_out, int out_size)
{
    const float* x     = (const float*)d_in[0];
    const float* Wqkv  = (const float*)d_in[1];
    const float* bqkv  = (const float*)d_in[2];
    const float* Wout  = (const float*)d_in[3];
    const float* bout  = (const float*)d_in[4];
    float* out = (float*)d_out;

    __half *x16 = nullptr, *wqkvT = nullptr, *woutT = nullptr, *y16 = nullptr;
    cudaGetSymbolAddress((void**)&x16, g_x16);
    cudaGetSymbolAddress((void**)&wqkvT, g_wqkvT16);
    cudaGetSymbolAddress((void**)&woutT, g_woutT16);
    cudaGetSymbolAddress((void**)&y16, g_y16);

    cudaFuncSetAttribute(gemm_f16<0>,
                         cudaFuncAttributeMaxDynamicSharedMemorySize, GEMM_SMEM);
    cudaFuncSetAttribute(gemm_f16<1>,
                         cudaFuncAttributeMaxDynamicSharedMemorySize, GEMM_SMEM);
    cudaFuncSetAttribute(attn_kernel,
                         cudaFuncAttributeMaxDynamicSharedMemorySize, ATTN_SMEM);

    // 0) prep: x -> half; W^T -> half
    to_half<<<(B_ * T_ * C_ / 4 + 255) / 256, 256>>>(x, x16, B_ * T_ * C_ / 4);
    transpose_half<<<dim3(3 * C_ / 32, C_ / 32), dim3(32, 8)>>>(Wqkv, wqkvT, C_, 3 * C_);
    transpose_half<<<dim3(C_ / 32, C_ / 32), dim3(32, 8)>>>(Wout, woutT, C_, C_);

    // 1) QKV projection -> q/k (BHTD) + vt (BHDT), half
    gemm_f16<0><<<dim3(3 * C_ / 128, B_ * T_ / 128), 256, GEMM_SMEM>>>(
        x16, wqkvT, bqkv, nullptr, 3 * C_);

    // 2) Causal flash attention -> g_y16
    attn_kernel<<<dim3(BH_, T_ / 64), 128, ATTN_SMEM>>>();

    // 3) Output projection -> out (fp32)
    gemm_f16<1><<<dim3(C_ / 128, B_ * T_ / 128), 256, GEMM_SMEM>>>(
        y16, woutT, bout, out, C_);
}

// round 7
// speedup vs baseline: 3.2618x; 1.0101x over previous
#include <cuda_runtime.h>
#include <cuda_fp16.h>
#include <cstdint>
#include <math.h>

// Problem constants
#define B_ 4
#define T_ 2048
#define C_ 1024
#define H_ 16
#define D_ 64
#define BH_ (B_ * H_)

// Scratch (device globals -- no allocation allowed)
__device__ __half g_q16[BH_ * T_ * D_];     // [B,H,T,D]
__device__ __half g_k16[BH_ * T_ * D_];     // [B,H,T,D]
__device__ __half g_vt16[BH_ * D_ * T_];    // [B,H,D,T]  (V transposed)
__device__ __half g_y16[B_ * T_ * C_];      // [B,T,C]
__device__ __half g_x16[B_ * T_ * C_];      // x -> half
__device__ __half g_wqkvT16[3 * C_ * C_];   // [3C, C] = W_qkv^T
__device__ __half g_woutT16[C_ * C_];       // [C, C]  = W_out^T

// ---------------------------------------------------------------------------
// Helpers
// ---------------------------------------------------------------------------
__device__ __forceinline__ uint32_t smem_u32(const void* p) {
    return (uint32_t)__cvta_generic_to_shared(p);
}

__device__ __forceinline__ float ex2f(float x) {
    float y;
    asm("ex2.approx.f32 %0, %1;" : "=f"(y) : "f"(x));
    return y;
}

__device__ __forceinline__ void mma_f16(float d[4], const uint32_t a[4],
                                        const uint32_t b[2], const float c[4]) {
    asm volatile(
        "mma.sync.aligned.m16n8k16.row.col.f32.f16.f16.f32 "
        "{%0,%1,%2,%3},{%4,%5,%6,%7},{%8,%9},{%10,%11,%12,%13};"
        : "=f"(d[0]), "=f"(d[1]), "=f"(d[2]), "=f"(d[3])
        : "r"(a[0]), "r"(a[1]), "r"(a[2]), "r"(a[3]),
          "r"(b[0]), "r"(b[1]),
          "f"(c[0]), "f"(c[1]), "f"(c[2]), "f"(c[3]));
}

__device__ __forceinline__ void ldsm_x4(uint32_t d[4], uint32_t saddr) {
    asm volatile(
        "ldmatrix.sync.aligned.m8n8.x4.shared.b16 {%0,%1,%2,%3}, [%4];"
        : "=r"(d[0]), "=r"(d[1]), "=r"(d[2]), "=r"(d[3]) : "r"(saddr));
}

__device__ __forceinline__ void cp_async16(uint32_t dst, const void* src) {
    asm volatile("cp.async.cg.shared.global [%0], [%1], 16;"
                 :: "r"(dst), "l"(src) : "memory");
}
__device__ __forceinline__ void cp_commit() {
    asm volatile("cp.async.commit_group;" ::: "memory");
}
template <int N>
__device__ __forceinline__ void cp_wait() {
    asm volatile("cp.async.wait_group %0;" :: "n"(N) : "memory");
}

// ---------------------------------------------------------------------------
// Prep kernels: fp32 -> fp16 copies / transposes
// ---------------------------------------------------------------------------
__global__ void to_half(const float* __restrict__ in, __half* __restrict__ out, int n4) {
    int i = blockIdx.x * blockDim.x + threadIdx.x;
    if (i < n4) {
        float4 v = ((const float4*)in)[i];
        __half2* o = (__half2*)(out + i * 4);
        o[0] = __floats2half2_rn(v.x, v.y);
        o[1] = __floats2half2_rn(v.z, v.w);
    }
}

// in: [R, Ccols] fp32 row-major -> out: [Ccols, R] half row-major
__global__ void transpose_half(const float* __restrict__ in, __half* __restrict__ out,
                               int R, int Ccols) {
    __shared__ float t[32][33];
    int bx = blockIdx.x * 32;
    int by = blockIdx.y * 32;
    int x = threadIdx.x, y = threadIdx.y;
#pragma unroll
    for (int j = 0; j < 32; j += 8)
        t[y + j][x] = in[(size_t)(by + y + j) * Ccols + bx + x];
    __syncthreads();
#pragma unroll
    for (int j = 0; j < 32; j += 8)
        out[(size_t)(bx + y + j) * R + by + x] = __float2half_rn(t[x][y + j]);
}

// ---------------------------------------------------------------------------
// FP16 GEMM: C[M, N] = A[M, 1024] @ Bt[N, 1024]^T + bias  (fp32 accumulate)
// BM=128 BN=128 BK=64 halves, 128 threads (4 warps, 2x2), warp tile 64x64.
// Per k16 step: 8 LDSM.x4 per 32 MMA. cp.async 3-stage, 1 sync/iter.
// MODE 0: convert to half + scatter q/k (BHTD) and vt (BHDT).
// MODE 1: fp32 row-major store + bias.
// ---------------------------------------------------------------------------
#define GKT 16                    // k-tiles (K=1024 / 64)
#define STAGE_B 16384             // 128 rows x 128B
#define GEMM_SMEM (6 * STAGE_B)   // 3 stages x (A+B) = 98304

template <int MODE>
__global__ __launch_bounds__(128, 2) void gemm_f16(
    const __half* __restrict__ Ag, const __half* __restrict__ Bg,
    const float* __restrict__ bias, float* __restrict__ Cout, int N)
{
    extern __shared__ char smem[];
    const uint32_t sA = smem_u32(smem);
    const uint32_t sB = sA + 3 * STAGE_B;

    const int tid  = threadIdx.x;
    const int lane = tid & 31;
    const int wid  = tid >> 5;
    const int wr   = (wid >> 1) * 64;     // warp row offset (2x2 warp grid)
    const int wc   = (wid & 1) * 64;      // warp col offset
    const int m0   = blockIdx.y * 128;
    const int n0   = blockIdx.x * 128;

    const int lr = tid >> 3;      // + i*16 (8 iters cover 128 rows)
    const int lg = tid & 7;       // 16B group (8 halves)

    auto issue = [&](int kt) {
        const int s = kt % 3;
#pragma unroll
        for (int i = 0; i < 8; i++) {
            int r = lr + i * 16;
            uint32_t off = r * 128 + ((lg ^ (r & 7)) << 4);
            cp_async16(sA + s * STAGE_B + off,
                       Ag + (size_t)(m0 + r) * 1024 + kt * 64 + lg * 8);
            cp_async16(sB + s * STAGE_B + off,
                       Bg + (size_t)(n0 + r) * 1024 + kt * 64 + lg * 8);
        }
        cp_commit();
    };

    // fragment lane mapping
    const int arow  = wr + (lane & 7) + 8 * ((lane >> 3) & 1);
    const int kha   = lane >> 4;
    const int brow0 = wc + (lane & 7) + 8 * (lane >> 4);
    const int khb   = (lane >> 3) & 1;

    float acc[4][8][4];
#pragma unroll
    for (int mi = 0; mi < 4; mi++)
#pragma unroll
        for (int ni = 0; ni < 8; ni++)
#pragma unroll
            for (int r = 0; r < 4; r++) acc[mi][ni][r] = 0.0f;

    issue(0);
    issue(1);

    for (int kt = 0; kt < GKT; kt++) {
        if (kt + 1 < GKT) cp_wait<1>(); else cp_wait<0>();
        __syncthreads();
        if (kt + 2 < GKT) issue(kt + 2);

        const int s = kt % 3;
        const uint32_t aS = sA + s * STAGE_B;
        const uint32_t bS = sB + s * STAGE_B;

#pragma unroll
        for (int kk = 0; kk < 4; kk++) {      // 4 x k16 = 64 k-depth
            uint32_t af[4][4];
#pragma unroll
            for (int mi = 0; mi < 4; mi++) {
                int r = arow + mi * 16;
                uint32_t addr = aS + r * 128 +
                                ((((kk << 1) | kha) ^ (r & 7)) << 4);
                ldsm_x4(af[mi], addr);
            }
            uint32_t bf[8][2];
#pragma unroll
            for (int p = 0; p < 4; p++) {
                int r = brow0 + p * 16;
                uint32_t addr = bS + r * 128 +
                                ((((kk << 1) | khb) ^ (r & 7)) << 4);
                uint32_t d[4];
                ldsm_x4(d, addr);
                bf[2 * p][0] = d[0]; bf[2 * p][1] = d[1];
                bf[2 * p + 1][0] = d[2]; bf[2 * p + 1][1] = d[3];
            }
#pragma unroll
            for (int mi = 0; mi < 4; mi++)
#pragma unroll
                for (int ni = 0; ni < 8; ni++)
                    mma_f16(acc[mi][ni], af[mi], bf[ni], acc[mi][ni]);
        }
        // no trailing sync: next iter's top sync protects stage reuse
    }

    // Epilogue
    const int g  = lane >> 2;
    const int tg = lane & 3;
#pragma unroll
    for (int mi = 0; mi < 4; mi++) {
#pragma unroll
        for (int ni = 0; ni < 8; ni++) {
#pragma unroll
            for (int r = 0; r < 4; r++) {
                int row = m0 + wr + mi * 16 + g + ((r >> 1) ? 8 : 0);
                int col = n0 + wc + ni * 8 + tg * 2 + (r & 1);
                float v = acc[mi][ni][r] + __ldg(&bias[col]);
                if (MODE == 0) {
                    __half hv = __float2half_rn(v);
                    int b = row >> 11;
                    int t = row & (T_ - 1);
                    int which = col >> 10;
                    int rr = col & (C_ - 1);
                    int h = rr >> 6;
                    int d = rr & 63;
                    size_t bhh = (size_t)(b * H_ + h);
                    if (which == 2) {
                        g_vt16[(bhh * D_ + d) * T_ + t] = hv;
                    } else {
                        __half* dst = (which == 0) ? g_q16 : g_k16;
                        dst[(bhh * T_ + t) * D_ + d] = hv;
                    }
                } else {
                    Cout[(size_t)row * N + col] = v;
                }
            }
        }
    }
}

// ---------------------------------------------------------------------------
// Flash attention (causal), fp16 mma, BQ=64 BKV=64, 128 threads (4 warps).
// Tiles: 64 rows x 128B (64 halves), swizzled; all fragments via ldmatrix.
// K + Vt double-buffered via cp.async. Softmax fp32, base-2.
// qi reversed (longest CTAs first) for wave balance.
// ---------------------------------------------------------------------------
#define ATG 8192                         // one tile: 64 x 128B
#define AQ_OFF 0
#define AK_OFF ATG                       // + s*ATG   (2 stages)
#define AV_OFF (3 * ATG)                 // + s*ATG   (2 stages)
#define AP_OFF (5 * ATG)
#define ATTN_SMEM (6 * ATG)              // 49152 bytes

__global__ __launch_bounds__(128, 4) void attn_kernel()
{
    extern __shared__ char smc[];
    const uint32_t sQ = smem_u32(smc);

    const int bh  = blockIdx.x;
    const int b   = bh >> 4;
    const int h   = bh & 15;
    const int qi  = (T_ / 64 - 1) - blockIdx.y;   // longest-first scheduling
    const int tid = threadIdx.x;
    const int lane = tid & 31;
    const int wid  = tid >> 5;
    const int g    = lane >> 2;
    const int tg   = lane & 3;

    const __half* Qg  = g_q16  + ((size_t)bh * T_ + qi * 64) * D_;
    const __half* Kg  = g_k16  + (size_t)bh * T_ * D_;
    const __half* Vtg = g_vt16 + (size_t)bh * D_ * T_;

    // Q tile -> swizzled smem
#pragma unroll
    for (int it = 0; it < 4; it++) {
        int i = tid + it * 128;
        int r = i >> 3, gg = i & 7;
        uint4 v = *(const uint4*)&Qg[r * 64 + gg * 8];
        *(uint4*)(smc + r * 128 + ((gg ^ (r & 7)) << 4)) = v;
    }

    auto issue = [&](int j, int s) {
#pragma unroll
        for (int it = 0; it < 4; it++) {
            int i = tid + it * 128;
            int r = i >> 3, gg = i & 7;
            uint32_t sw = r * 128 + ((gg ^ (r & 7)) << 4);
            cp_async16(sQ + AK_OFF + s * ATG + sw,
                       Kg + ((size_t)j * 64 + r) * 64 + gg * 8);
            cp_async16(sQ + AV_OFF + s * ATG + sw,
                       Vtg + (size_t)r * T_ + j * 64 + gg * 8);
        }
        cp_commit();
    };

    issue(0, 0);
    if (qi >= 1) issue(1, 1);

    // fragment lane constants
    const int qrow = wid * 16 + (lane & 7) + 8 * ((lane >> 3) & 1);
    const int khq  = lane >> 4;
    const int qxk  = qrow & 7;
    const uint32_t qbase = sQ + AQ_OFF + qrow * 128;
    const uint32_t pbase = sQ + AP_OFF + qrow * 128;
    const int brow = (lane & 7) + 8 * (lane >> 4);    // + p*16
    const int khb  = (lane >> 3) & 1;

    float O[8][4];
#pragma unroll
    for (int ni = 0; ni < 8; ni++)
#pragma unroll
        for (int r = 0; r < 4; r++) O[ni][r] = 0.0f;
    float mrow0 = -1e30f, mrow1 = -1e30f;
    float lrow0 = 0.0f,   lrow1 = 0.0f;

    const int rloc = wid * 16 + g;
    const float scale = 0.125f * 1.4426950408889634f;   // 1/sqrt(D) * log2(e)

    for (int j = 0; j <= qi; j++) {
        const int s = j & 1;
        if (j < qi) cp_wait<1>(); else cp_wait<0>();
        __syncthreads();

        const uint32_t kS = sQ + AK_OFF + s * ATG;
        const uint32_t vS = sQ + AV_OFF + s * ATG;

        // S = Q K^T  (fp32 accum)
        float sfr[8][4];
#pragma unroll
        for (int ni = 0; ni < 8; ni++)
#pragma unroll
            for (int r = 0; r < 4; r++) sfr[ni][r] = 0.0f;

#pragma unroll
        for (int kk = 0; kk < 4; kk++) {
            uint32_t af[4];
            ldsm_x4(af, qbase + ((((kk << 1) | khq) ^ qxk) << 4));
            uint32_t bf[8][2];
#pragma unroll
            for (int p = 0; p < 4; p++) {
                int r = brow + p * 16;
                uint32_t d[4];
                ldsm_x4(d, kS + r * 128 + ((((kk << 1) | khb) ^ (r & 7)) << 4));
                bf[2 * p][0] = d[0]; bf[2 * p][1] = d[1];
                bf[2 * p + 1][0] = d[2]; bf[2 * p + 1][1] = d[3];
            }
#pragma unroll
            for (int ni = 0; ni < 8; ni++)
                mma_f16(sfr[ni], af, bf[ni], sfr[ni]);
        }

        // Scale (base-2) + causal mask (diagonal tile only)
        const bool diag = (j == qi);
        const int rowg0 = qi * 64 + rloc;
        const int rowg1 = rowg0 + 8;
#pragma unroll
        for (int ni = 0; ni < 8; ni++) {
#pragma unroll
            for (int r = 0; r < 4; r++) {
                float sv = sfr[ni][r] * scale;
                if (diag) {
                    int colg = j * 64 + ni * 8 + tg * 2 + (r & 1);
                    int rowg = (r >> 1) ? rowg1 : rowg0;
                    if (colg > rowg) sv = -1e30f;
                }
                sfr[ni][r] = sv;
            }
        }

        // Online softmax (base-2; two rows per thread)
        float mx0 = -1e30f, mx1 = -1e30f;
#pragma unroll
        for (int ni = 0; ni < 8; ni++) {
            mx0 = fmaxf(mx0, fmaxf(sfr[ni][0], sfr[ni][1]));
            mx1 = fmaxf(mx1, fmaxf(sfr[ni][2], sfr[ni][3]));
        }
        mx0 = fmaxf(mx0, __shfl_xor_sync(0xffffffffu, mx0, 1));
        mx0 = fmaxf(mx0, __shfl_xor_sync(0xffffffffu, mx0, 2));
        mx1 = fmaxf(mx1, __shfl_xor_sync(0xffffffffu, mx1, 1));
        mx1 = fmaxf(mx1, __shfl_xor_sync(0xffffffffu, mx1, 2));

        float mn0 = fmaxf(mrow0, mx0);
        float mn1 = fmaxf(mrow1, mx1);
        float a0 = ex2f(mrow0 - mn0);
        float a1 = ex2f(mrow1 - mn1);

        float rs0 = 0.0f, rs1 = 0.0f;
#pragma unroll
        for (int ni = 0; ni < 8; ni++) {
            float p0 = ex2f(sfr[ni][0] - mn0); sfr[ni][0] = p0; rs0 += p0;
            float p1 = ex2f(sfr[ni][1] - mn0); sfr[ni][1] = p1; rs0 += p1;
            float p2 = ex2f(sfr[ni][2] - mn1); sfr[ni][2] = p2; rs1 += p2;
            float p3 = ex2f(sfr[ni][3] - mn1); sfr[ni][3] = p3; rs1 += p3;
        }
        rs0 += __shfl_xor_sync(0xffffffffu, rs0, 1);
        rs0 += __shfl_xor_sync(0xffffffffu, rs0, 2);
        rs1 += __shfl_xor_sync(0xffffffffu, rs1, 1);
        rs1 += __shfl_xor_sync(0xffffffffu, rs1, 2);

        lrow0 = lrow0 * a0 + rs0;
        lrow1 = lrow1 * a1 + rs1;
        mrow0 = mn0;
        mrow1 = mn1;

#pragma unroll
        for (int ni = 0; ni < 8; ni++) {
            O[ni][0] *= a0; O[ni][1] *= a0;
            O[ni][2] *= a1; O[ni][3] *= a1;
        }

        // P -> swizzled smem as half2 (warp-private rows)
        {
            const int xk = rloc & 7;
#pragma unroll
            for (int ni = 0; ni < 8; ni++) {
                uint32_t o0 = AP_OFF + rloc * 128 + ((ni ^ xk) << 4) + tg * 4;
                *(__half2*)(smc + o0) = __floats2half2_rn(sfr[ni][0], sfr[ni][1]);
                *(__half2*)(smc + o0 + 8 * 128) = __floats2half2_rn(sfr[ni][2], sfr[ni][3]);
            }
        }
        __syncwarp();

        // O += P @ V   (Vt fragments via ldmatrix)
#pragma unroll
        for (int kk = 0; kk < 4; kk++) {
            uint32_t af[4];
            ldsm_x4(af, pbase + ((((kk << 1) | khq) ^ qxk) << 4));
            uint32_t bf[8][2];
#pragma unroll
            for (int p = 0; p < 4; p++) {
                int r = brow + p * 16;
                uint32_t d[4];
                ldsm_x4(d, vS + r * 128 + ((((kk << 1) | khb) ^ (r & 7)) << 4));
                bf[2 * p][0] = d[0]; bf[2 * p][1] = d[1];
                bf[2 * p + 1][0] = d[2]; bf[2 * p + 1][1] = d[3];
            }
#pragma unroll
            for (int ni = 0; ni < 8; ni++)
                mma_f16(O[ni], af, bf[ni], O[ni]);
        }
        __syncthreads();
        if (j + 2 <= qi) issue(j + 2, s);
    }

    // Epilogue: O /= l, convert to half, write [B,T,H,D]
    float il0 = 1.0f / lrow0;
    float il1 = 1.0f / lrow1;
    int t0 = qi * 64 + rloc;
#pragma unroll
    for (int ni = 0; ni < 8; ni++) {
        int d = ni * 8 + tg * 2;
        size_t base0 = ((size_t)(b * T_ + t0    ) * H_ + h) * D_ + d;
        size_t base1 = ((size_t)(b * T_ + t0 + 8) * H_ + h) * D_ + d;
        *(__half2*)&g_y16[base0] = __floats2half2_rn(O[ni][0] * il0, O[ni][1] * il0);
        *(__half2*)&g_y16[base1] = __floats2half2_rn(O[ni][2] * il1, O[ni][3] * il1);
    }
}

// ---------------------------------------------------------------------------
// Launch
// ---------------------------------------------------------------------------
extern "C" void kernel_launch(void* const* d_in, const int* in_sizes, int n_in,
                              void* d_out, int out_size)
{
    const float* x     = (const float*)d_in[0];
    const float* Wqkv  = (const float*)d_in[1];
    const float* bqkv  = (const float*)d_in[2];
    const float* Wout  = (const float*)d_in[3];
    const float* bout  = (const float*)d_in[4];
    float* out = (float*)d_out;

    __half *x16 = nullptr, *wqkvT = nullptr, *woutT = nullptr, *y16 = nullptr;
    cudaGetSymbolAddress((void**)&x16, g_x16);
    cudaGetSymbolAddress((void**)&wqkvT, g_wqkvT16);
    cudaGetSymbolAddress((void**)&woutT, g_woutT16);
    cudaGetSymbolAddress((void**)&y16, g_y16);

    cudaFuncSetAttribute(gemm_f16<0>,
                         cudaFuncAttributeMaxDynamicSharedMemorySize, GEMM_SMEM);
    cudaFuncSetAttribute(gemm_f16<1>,
                         cudaFuncAttributeMaxDynamicSharedMemorySize, GEMM_SMEM);
    cudaFuncSetAttribute(attn_kernel,
                         cudaFuncAttributeMaxDynamicSharedMemorySize, ATTN_SMEM);

    // 0) prep: x -> half; W^T -> half
    to_half<<<(B_ * T_ * C_ / 4 + 255) / 256, 256>>>(x, x16, B_ * T_ * C_ / 4);
    transpose_half<<<dim3(3 * C_ / 32, C_ / 32), dim3(32, 8)>>>(Wqkv, wqkvT, C_, 3 * C_);
    transpose_half<<<dim3(C_ / 32, C_ / 32), dim3(32, 8)>>>(Wout, woutT, C_, C_);

    // 1) QKV projection -> q/k (BHTD) + vt (BHDT), half
    gemm_f16<0><<<dim3(3 * C_ / 128, B_ * T_ / 128), 128, GEMM_SMEM>>>(
        x16, wqkvT, bqkv, nullptr, 3 * C_);

    // 2) Causal flash attention -> g_y16
    attn_kernel<<<dim3(BH_, T_ / 64), 128, ATTN_SMEM>>>();

    // 3) Output projection -> out (fp32)
    gemm_f16<1><<<dim3(C_ / 128, B_ * T_ / 128), 128, GEMM_SMEM>>>(
        y16, woutT, bout, out, C_);
}

// round 8
// speedup vs baseline: 3.3238x; 1.0190x over previous
#include <cuda_runtime.h>
#include <cuda_fp16.h>
#include <cstdint>
#include <math.h>

// Problem constants
#define B_ 4
#define T_ 2048
#define C_ 1024
#define H_ 16
#define D_ 64
#define BH_ (B_ * H_)

// Scratch (device globals -- no allocation allowed)
__device__ __half g_q16[BH_ * T_ * D_];     // [B,H,T,D]
__device__ __half g_k16[BH_ * T_ * D_];     // [B,H,T,D]
__device__ __half g_vt16[BH_ * D_ * T_];    // [B,H,D,T]  (V transposed)
__device__ __half g_y16[B_ * T_ * C_];      // [B,T,C]
__device__ __half g_x16[B_ * T_ * C_];      // x -> half
__device__ __half g_wqkvT16[3 * C_ * C_];   // [3C, C] = W_qkv^T
__device__ __half g_woutT16[C_ * C_];       // [C, C]  = W_out^T

// ---------------------------------------------------------------------------
// Helpers
// ---------------------------------------------------------------------------
__device__ __forceinline__ uint32_t smem_u32(const void* p) {
    return (uint32_t)__cvta_generic_to_shared(p);
}

__device__ __forceinline__ float ex2f(float x) {
    float y;
    asm("ex2.approx.f32 %0, %1;" : "=f"(y) : "f"(x));
    return y;
}

__device__ __forceinline__ void mma_f16(float d[4], const uint32_t a[4],
                                        const uint32_t b[2], const float c[4]) {
    asm volatile(
        "mma.sync.aligned.m16n8k16.row.col.f32.f16.f16.f32 "
        "{%0,%1,%2,%3},{%4,%5,%6,%7},{%8,%9},{%10,%11,%12,%13};"
        : "=f"(d[0]), "=f"(d[1]), "=f"(d[2]), "=f"(d[3])
        : "r"(a[0]), "r"(a[1]), "r"(a[2]), "r"(a[3]),
          "r"(b[0]), "r"(b[1]),
          "f"(c[0]), "f"(c[1]), "f"(c[2]), "f"(c[3]));
}

__device__ __forceinline__ void ldsm_x4(uint32_t d[4], uint32_t saddr) {
    asm volatile(
        "ldmatrix.sync.aligned.m8n8.x4.shared.b16 {%0,%1,%2,%3}, [%4];"
        : "=r"(d[0]), "=r"(d[1]), "=r"(d[2]), "=r"(d[3]) : "r"(saddr));
}

__device__ __forceinline__ void cp_async16(uint32_t dst, const void* src) {
    asm volatile("cp.async.cg.shared.global [%0], [%1], 16;"
                 :: "r"(dst), "l"(src) : "memory");
}
__device__ __forceinline__ void cp_commit() {
    asm volatile("cp.async.commit_group;" ::: "memory");
}
template <int N>
__device__ __forceinline__ void cp_wait() {
    asm volatile("cp.async.wait_group %0;" :: "n"(N) : "memory");
}

// ---------------------------------------------------------------------------
// Prep kernels: fp32 -> fp16 copies / transposes
// ---------------------------------------------------------------------------
__global__ void to_half(const float* __restrict__ in, __half* __restrict__ out, int n4) {
    int i = blockIdx.x * blockDim.x + threadIdx.x;
    if (i < n4) {
        float4 v = ((const float4*)in)[i];
        __half2* o = (__half2*)(out + i * 4);
        o[0] = __floats2half2_rn(v.x, v.y);
        o[1] = __floats2half2_rn(v.z, v.w);
    }
}

// in: [R, Ccols] fp32 row-major -> out: [Ccols, R] half row-major
__global__ void transpose_half(const float* __restrict__ in, __half* __restrict__ out,
                               int R, int Ccols) {
    __shared__ float t[32][33];
    int bx = blockIdx.x * 32;
    int by = blockIdx.y * 32;
    int x = threadIdx.x, y = threadIdx.y;
#pragma unroll
    for (int j = 0; j < 32; j += 8)
        t[y + j][x] = in[(size_t)(by + y + j) * Ccols + bx + x];
    __syncthreads();
#pragma unroll
    for (int j = 0; j < 32; j += 8)
        out[(size_t)(bx + y + j) * R + by + x] = __float2half_rn(t[x][y + j]);
}

// ---------------------------------------------------------------------------
// FP16 GEMM (R6 config): C[M, N] = A[M,1024] @ Bt[N,1024]^T + bias (fp32 acc)
// BM=128 BN=128 BK=64 halves, 256 threads (8 warps 2x4), warp tile 64x32.
// cp.async 3-stage, 1 sync/iter, ldmatrix both operands.
// MODE 0: convert to half + scatter q/k (BHTD) and vt (BHDT).
// MODE 1: fp32 row-major store + bias.
// ---------------------------------------------------------------------------
#define GKT 16                    // k-tiles (K=1024 / 64)
#define STAGE_B 16384             // 128 rows x 128B
#define GEMM_SMEM (6 * STAGE_B)   // 3 stages x (A+B) = 98304

template <int MODE>
__global__ __launch_bounds__(256, 2) void gemm_f16(
    const __half* __restrict__ Ag, const __half* __restrict__ Bg,
    const float* __restrict__ bias, float* __restrict__ Cout, int N)
{
    extern __shared__ char smem[];
    const uint32_t sA = smem_u32(smem);
    const uint32_t sB = sA + 3 * STAGE_B;

    const int tid  = threadIdx.x;
    const int lane = tid & 31;
    const int wid  = tid >> 5;
    const int wr   = (wid >> 2) * 64;
    const int wc   = (wid & 3) * 32;
    const int m0   = blockIdx.y * 128;
    const int n0   = blockIdx.x * 128;

    const int lr = tid >> 3;      // + i*32
    const int lg = tid & 7;       // 16B group (8 halves)

    auto issue = [&](int kt) {
        const int s = kt % 3;
#pragma unroll
        for (int i = 0; i < 4; i++) {
            int r = lr + i * 32;
            uint32_t off = r * 128 + ((lg ^ (r & 7)) << 4);
            cp_async16(sA + s * STAGE_B + off,
                       Ag + (size_t)(m0 + r) * 1024 + kt * 64 + lg * 8);
            cp_async16(sB + s * STAGE_B + off,
                       Bg + (size_t)(n0 + r) * 1024 + kt * 64 + lg * 8);
        }
        cp_commit();
    };

    const int arow  = wr + (lane & 7) + 8 * ((lane >> 3) & 1);
    const int kha   = lane >> 4;
    const int brow0 = wc + (lane & 7) + 8 * (lane >> 4);
    const int khb   = (lane >> 3) & 1;

    float acc[4][4][4];
#pragma unroll
    for (int mi = 0; mi < 4; mi++)
#pragma unroll
        for (int ni = 0; ni < 4; ni++)
#pragma unroll
            for (int r = 0; r < 4; r++) acc[mi][ni][r] = 0.0f;

    issue(0);
    issue(1);

    for (int kt = 0; kt < GKT; kt++) {
        if (kt + 1 < GKT) cp_wait<1>(); else cp_wait<0>();
        __syncthreads();
        if (kt + 2 < GKT) issue(kt + 2);

        const int s = kt % 3;
        const uint32_t aS = sA + s * STAGE_B;
        const uint32_t bS = sB + s * STAGE_B;

#pragma unroll
        for (int kk = 0; kk < 4; kk++) {
            uint32_t af[4][4];
#pragma unroll
            for (int mi = 0; mi < 4; mi++) {
                int r = arow + mi * 16;
                uint32_t addr = aS + r * 128 +
                                ((((kk << 1) | kha) ^ (r & 7)) << 4);
                ldsm_x4(af[mi], addr);
            }
            uint32_t bf[4][2];
#pragma unroll
            for (int p = 0; p < 2; p++) {
                int r = brow0 + p * 16;
                uint32_t addr = bS + r * 128 +
                                ((((kk << 1) | khb) ^ (r & 7)) << 4);
                uint32_t d[4];
                ldsm_x4(d, addr);
                bf[2 * p][0] = d[0]; bf[2 * p][1] = d[1];
                bf[2 * p + 1][0] = d[2]; bf[2 * p + 1][1] = d[3];
            }
#pragma unroll
            for (int mi = 0; mi < 4; mi++)
#pragma unroll
                for (int ni = 0; ni < 4; ni++)
                    mma_f16(acc[mi][ni], af[mi], bf[ni], acc[mi][ni]);
        }
    }

    // Epilogue
    const int g  = lane >> 2;
    const int tg = lane & 3;
#pragma unroll
    for (int mi = 0; mi < 4; mi++) {
#pragma unroll
        for (int ni = 0; ni < 4; ni++) {
#pragma unroll
            for (int r = 0; r < 4; r++) {
                int row = m0 + wr + mi * 16 + g + ((r >> 1) ? 8 : 0);
                int col = n0 + wc + ni * 8 + tg * 2 + (r & 1);
                float v = acc[mi][ni][r] + __ldg(&bias[col]);
                if (MODE == 0) {
                    __half hv = __float2half_rn(v);
                    int b = row >> 11;
                    int t = row & (T_ - 1);
                    int which = col >> 10;
                    int rr = col & (C_ - 1);
                    int h = rr >> 6;
                    int d = rr & 63;
                    size_t bhh = (size_t)(b * H_ + h);
                    if (which == 2) {
                        g_vt16[(bhh * D_ + d) * T_ + t] = hv;
                    } else {
                        __half* dst = (which == 0) ? g_q16 : g_k16;
                        dst[(bhh * T_ + t) * D_ + d] = hv;
                    }
                } else {
                    Cout[(size_t)row * N + col] = v;
                }
            }
        }
    }
}

// ---------------------------------------------------------------------------
// Flash attention (causal), fp16 mma, BQ=128 BKV=64, 256 threads (8 warps),
// each warp owns a 16-row q slab. Tiles 128B-rows swizzled, all ldmatrix.
// K + Vt double-buffered cp.async. Softmax fp32 base-2. LPT (qi reversed).
// smem 64KB -> 2 CTAs/SM.
// ---------------------------------------------------------------------------
#define AQB 16384                        // Q: 128 rows x 128B
#define AKV 8192                         // K/Vt tile: 64 rows x 128B
#define AQ_OFF 0
#define AK_OFF AQB                       // + s*AKV   (2 stages)
#define AV_OFF (AQB + 2 * AKV)           // + s*AKV   (2 stages)
#define AP_OFF (AQB + 4 * AKV)           // P: 128 rows x 128B
#define ATTN_SMEM (2 * AQB + 4 * AKV)    // 65536 bytes

__global__ __launch_bounds__(256, 2) void attn_kernel()
{
    extern __shared__ char smc[];
    const uint32_t sQ = smem_u32(smc);

    const int bh  = blockIdx.x;
    const int b   = bh >> 4;
    const int h   = bh & 15;
    const int qi  = (T_ / 128 - 1) - blockIdx.y;   // longest-first
    const int tid = threadIdx.x;
    const int lane = tid & 31;
    const int wid  = tid >> 5;
    const int g    = lane >> 2;
    const int tg   = lane & 3;

    const __half* Qg  = g_q16  + ((size_t)bh * T_ + qi * 128) * D_;
    const __half* Kg  = g_k16  + (size_t)bh * T_ * D_;
    const __half* Vtg = g_vt16 + (size_t)bh * D_ * T_;

    // Q tile (128x64 halves) -> swizzled smem
#pragma unroll
    for (int it = 0; it < 4; it++) {
        int i = tid + it * 256;
        int r = i >> 3, gg = i & 7;
        uint4 v = *(const uint4*)&Qg[r * 64 + gg * 8];
        *(uint4*)(smc + r * 128 + ((gg ^ (r & 7)) << 4)) = v;
    }

    auto issue = [&](int j, int s) {
#pragma unroll
        for (int it = 0; it < 2; it++) {
            int i = tid + it * 256;
            int r = i >> 3, gg = i & 7;
            uint32_t sw = r * 128 + ((gg ^ (r & 7)) << 4);
            cp_async16(sQ + AK_OFF + s * AKV + sw,
                       Kg + ((size_t)j * 64 + r) * 64 + gg * 8);
            cp_async16(sQ + AV_OFF + s * AKV + sw,
                       Vtg + (size_t)r * T_ + j * 64 + gg * 8);
        }
        cp_commit();
    };

    const int jmax = 2 * qi + 1;
    issue(0, 0);
    issue(1, 1);

    // fragment lane constants
    const int qrow = wid * 16 + (lane & 7) + 8 * ((lane >> 3) & 1);
    const int khq  = lane >> 4;
    const int qxk  = qrow & 7;
    const uint32_t qbase = sQ + AQ_OFF + qrow * 128;
    const uint32_t pbase = sQ + AP_OFF + qrow * 128;
    const int brow = (lane & 7) + 8 * (lane >> 4);    // + p*16
    const int khb  = (lane >> 3) & 1;

    float O[8][4];
#pragma unroll
    for (int ni = 0; ni < 8; ni++)
#pragma unroll
        for (int r = 0; r < 4; r++) O[ni][r] = 0.0f;
    float mrow0 = -1e30f, mrow1 = -1e30f;
    float lrow0 = 0.0f,   lrow1 = 0.0f;

    const int rloc = wid * 16 + g;
    const float scale = 0.125f * 1.4426950408889634f;   // 1/sqrt(D) * log2(e)

    for (int j = 0; j <= jmax; j++) {
        const int s = j & 1;
        if (j < jmax) cp_wait<1>(); else cp_wait<0>();
        __syncthreads();

        const uint32_t kS = sQ + AK_OFF + s * AKV;
        const uint32_t vS = sQ + AV_OFF + s * AKV;

        // S = Q K^T  (fp32 accum)
        float sfr[8][4];
#pragma unroll
        for (int ni = 0; ni < 8; ni++)
#pragma unroll
            for (int r = 0; r < 4; r++) sfr[ni][r] = 0.0f;

#pragma unroll
        for (int kk = 0; kk < 4; kk++) {
            uint32_t af[4];
            ldsm_x4(af, qbase + ((((kk << 1) | khq) ^ qxk) << 4));
            uint32_t bf[8][2];
#pragma unroll
            for (int p = 0; p < 4; p++) {
                int r = brow + p * 16;
                uint32_t d[4];
                ldsm_x4(d, kS + r * 128 + ((((kk << 1) | khb) ^ (r & 7)) << 4));
                bf[2 * p][0] = d[0]; bf[2 * p][1] = d[1];
                bf[2 * p + 1][0] = d[2]; bf[2 * p + 1][1] = d[3];
            }
#pragma unroll
            for (int ni = 0; ni < 8; ni++)
                mma_f16(sfr[ni], af, bf[ni], sfr[ni]);
        }

        // Scale (base-2) + causal mask (last two kv tiles straddle diagonal)
        const bool diag = (j >= 2 * qi);
        const int rowg0 = qi * 128 + rloc;
        const int rowg1 = rowg0 + 8;
#pragma unroll
        for (int ni = 0; ni < 8; ni++) {
#pragma unroll
            for (int r = 0; r < 4; r++) {
                float sv = sfr[ni][r] * scale;
                if (diag) {
                    int colg = j * 64 + ni * 8 + tg * 2 + (r & 1);
                    int rowg = (r >> 1) ? rowg1 : rowg0;
                    if (colg > rowg) sv = -1e30f;
                }
                sfr[ni][r] = sv;
            }
        }

        // Online softmax (base-2; two rows per thread)
        float mx0 = -1e30f, mx1 = -1e30f;
#pragma unroll
        for (int ni = 0; ni < 8; ni++) {
            mx0 = fmaxf(mx0, fmaxf(sfr[ni][0], sfr[ni][1]));
            mx1 = fmaxf(mx1, fmaxf(sfr[ni][2], sfr[ni][3]));
        }
        mx0 = fmaxf(mx0, __shfl_xor_sync(0xffffffffu, mx0, 1));
        mx0 = fmaxf(mx0, __shfl_xor_sync(0xffffffffu, mx0, 2));
        mx1 = fmaxf(mx1, __shfl_xor_sync(0xffffffffu, mx1, 1));
        mx1 = fmaxf(mx1, __shfl_xor_sync(0xffffffffu, mx1, 2));

        float mn0 = fmaxf(mrow0, mx0);
        float mn1 = fmaxf(mrow1, mx1);
        float a0 = ex2f(mrow0 - mn0);
        float a1 = ex2f(mrow1 - mn1);

        float rs0 = 0.0f, rs1 = 0.0f;
#pragma unroll
        for (int ni = 0; ni < 8; ni++) {
            float p0 = ex2f(sfr[ni][0] - mn0); sfr[ni][0] = p0; rs0 += p0;
            float p1 = ex2f(sfr[ni][1] - mn0); sfr[ni][1] = p1; rs0 += p1;
            float p2 = ex2f(sfr[ni][2] - mn1); sfr[ni][2] = p2; rs1 += p2;
            float p3 = ex2f(sfr[ni][3] - mn1); sfr[ni][3] = p3; rs1 += p3;
        }
        rs0 += __shfl_xor_sync(0xffffffffu, rs0, 1);
        rs0 += __shfl_xor_sync(0xffffffffu, rs0, 2);
        rs1 += __shfl_xor_sync(0xffffffffu, rs1, 1);
        rs1 += __shfl_xor_sync(0xffffffffu, rs1, 2);

        lrow0 = lrow0 * a0 + rs0;
        lrow1 = lrow1 * a1 + rs1;
        mrow0 = mn0;
        mrow1 = mn1;

#pragma unroll
        for (int ni = 0; ni < 8; ni++) {
            O[ni][0] *= a0; O[ni][1] *= a0;
            O[ni][2] *= a1; O[ni][3] *= a1;
        }

        // P -> swizzled smem as half2 (warp-private 16-row slab)
        {
            const int xk = rloc & 7;
#pragma unroll
            for (int ni = 0; ni < 8; ni++) {
                uint32_t o0 = AP_OFF + rloc * 128 + ((ni ^ xk) << 4) + tg * 4;
                *(__half2*)(smc + o0) = __floats2half2_rn(sfr[ni][0], sfr[ni][1]);
                *(__half2*)(smc + o0 + 8 * 128) = __floats2half2_rn(sfr[ni][2], sfr[ni][3]);
            }
        }
        __syncwarp();

        // O += P @ V   (Vt fragments via ldmatrix)
#pragma unroll
        for (int kk = 0; kk < 4; kk++) {
            uint32_t af[4];
            ldsm_x4(af, pbase + ((((kk << 1) | khq) ^ qxk) << 4));
            uint32_t bf[8][2];
#pragma unroll
            for (int p = 0; p < 4; p++) {
                int r = brow + p * 16;
                uint32_t d[4];
                ldsm_x4(d, vS + r * 128 + ((((kk << 1) | khb) ^ (r & 7)) << 4));
                bf[2 * p][0] = d[0]; bf[2 * p][1] = d[1];
                bf[2 * p + 1][0] = d[2]; bf[2 * p + 1][1] = d[3];
            }
#pragma unroll
            for (int ni = 0; ni < 8; ni++)
                mma_f16(O[ni], af, bf[ni], O[ni]);
        }
        __syncthreads();
        if (j + 2 <= jmax) issue(j + 2, s);
    }

    // Epilogue: O /= l, convert to half, write [B,T,H,D]
    float il0 = 1.0f / lrow0;
    float il1 = 1.0f / lrow1;
    int t0 = qi * 128 + rloc;
#pragma unroll
    for (int ni = 0; ni < 8; ni++) {
        int d = ni * 8 + tg * 2;
        size_t base0 = ((size_t)(b * T_ + t0    ) * H_ + h) * D_ + d;
        size_t base1 = ((size_t)(b * T_ + t0 + 8) * H_ + h) * D_ + d;
        *(__half2*)&g_y16[base0] = __floats2half2_rn(O[ni][0] * il0, O[ni][1] * il0);
        *(__half2*)&g_y16[base1] = __floats2half2_rn(O[ni][2] * il1, O[ni][3] * il1);
    }
}

// ---------------------------------------------------------------------------
// Launch
// ---------------------------------------------------------------------------
extern "C" void kernel_launch(void* const* d_in, const int* in_sizes, int n_in,
                              void* d_out, int out_size)
{
    const float* x     = (const float*)d_in[0];
    const float* Wqkv  = (const float*)d_in[1];
    const float* bqkv  = (const float*)d_in[2];
    const float* Wout  = (const float*)d_in[3];
    const float* bout  = (const float*)d_in[4];
    float* out = (float*)d_out;

    __half *x16 = nullptr, *wqkvT = nullptr, *woutT = nullptr, *y16 = nullptr;
    cudaGetSymbolAddress((void**)&x16, g_x16);
    cudaGetSymbolAddress((void**)&wqkvT, g_wqkvT16);
    cudaGetSymbolAddress((void**)&woutT, g_woutT16);
    cudaGetSymbolAddress((void**)&y16, g_y16);

    cudaFuncSetAttribute(gemm_f16<0>,
                         cudaFuncAttributeMaxDynamicSharedMemorySize, GEMM_SMEM);
    cudaFuncSetAttribute(gemm_f16<1>,
                         cudaFuncAttributeMaxDynamicSharedMemorySize, GEMM_SMEM);
    cudaFuncSetAttribute(attn_kernel,
                         cudaFuncAttributeMaxDynamicSharedMemorySize, ATTN_SMEM);

    // 0) prep: x -> half; W^T -> half
    to_half<<<(B_ * T_ * C_ / 4 + 255) / 256, 256>>>(x, x16, B_ * T_ * C_ / 4);
    transpose_half<<<dim3(3 * C_ / 32, C_ / 32), dim3(32, 8)>>>(Wqkv, wqkvT, C_, 3 * C_);
    transpose_half<<<dim3(C_ / 32, C_ / 32), dim3(32, 8)>>>(Wout, woutT, C_, C_);

    // 1) QKV projection -> q/k (BHTD) + vt (BHDT), half
    gemm_f16<0><<<dim3(3 * C_ / 128, B_ * T_ / 128), 256, GEMM_SMEM>>>(
        x16, wqkvT, bqkv, nullptr, 3 * C_);

    // 2) Causal flash attention -> g_y16
    attn_kernel<<<dim3(BH_, T_ / 128), 256, ATTN_SMEM>>>();

    // 3) Output projection -> out (fp32)
    gemm_f16<1><<<dim3(C_ / 128, B_ * T_ / 128), 256, GEMM_SMEM>>>(
        y16, woutT, bout, out, C_);
}

// round 9
// speedup vs baseline: 3.4533x; 1.0390x over previous
#include <cuda_runtime.h>
#include <cuda_fp16.h>
#include <cstdint>
#include <math.h>

// Problem constants
#define B_ 4
#define T_ 2048
#define C_ 1024
#define H_ 16
#define D_ 64
#define BH_ (B_ * H_)

// Scratch (device globals -- no allocation allowed)
__device__ __half g_q16[BH_ * T_ * D_];     // [B,H,T,D]
__device__ __half g_k16[BH_ * T_ * D_];     // [B,H,T,D]
__device__ __half g_vt16[BH_ * D_ * T_];    // [B,H,D,T]  (V transposed)
__device__ __half g_y16[B_ * T_ * C_];      // [B,T,C]
__device__ __half g_x16[B_ * T_ * C_];      // x -> half
__device__ __half g_wqkvT16[3 * C_ * C_];   // [3C, C] = W_qkv^T
__device__ __half g_woutT16[C_ * C_];       // [C, C]  = W_out^T

// ---------------------------------------------------------------------------
// Helpers
// ---------------------------------------------------------------------------
__device__ __forceinline__ uint32_t smem_u32(const void* p) {
    return (uint32_t)__cvta_generic_to_shared(p);
}

__device__ __forceinline__ float ex2f(float x) {
    float y;
    asm("ex2.approx.f32 %0, %1;" : "=f"(y) : "f"(x));
    return y;
}

__device__ __forceinline__ uint32_t packh2(float a, float b) {
    __half2 h = __floats2half2_rn(a, b);
    return *(uint32_t*)&h;
}

__device__ __forceinline__ void mma_f16(float d[4], const uint32_t a[4],
                                        const uint32_t b[2], const float c[4]) {
    asm volatile(
        "mma.sync.aligned.m16n8k16.row.col.f32.f16.f16.f32 "
        "{%0,%1,%2,%3},{%4,%5,%6,%7},{%8,%9},{%10,%11,%12,%13};"
        : "=f"(d[0]), "=f"(d[1]), "=f"(d[2]), "=f"(d[3])
        : "r"(a[0]), "r"(a[1]), "r"(a[2]), "r"(a[3]),
          "r"(b[0]), "r"(b[1]),
          "f"(c[0]), "f"(c[1]), "f"(c[2]), "f"(c[3]));
}

__device__ __forceinline__ void ldsm_x4(uint32_t d[4], uint32_t saddr) {
    asm volatile(
        "ldmatrix.sync.aligned.m8n8.x4.shared.b16 {%0,%1,%2,%3}, [%4];"
        : "=r"(d[0]), "=r"(d[1]), "=r"(d[2]), "=r"(d[3]) : "r"(saddr));
}

__device__ __forceinline__ void cp_async16(uint32_t dst, const void* src) {
    asm volatile("cp.async.cg.shared.global [%0], [%1], 16;"
                 :: "r"(dst), "l"(src) : "memory");
}
__device__ __forceinline__ void cp_commit() {
    asm volatile("cp.async.commit_group;" ::: "memory");
}
template <int N>
__device__ __forceinline__ void cp_wait() {
    asm volatile("cp.async.wait_group %0;" :: "n"(N) : "memory");
}

// ---------------------------------------------------------------------------
// Prep kernels: fp32 -> fp16 copies / transposes
// ---------------------------------------------------------------------------
__global__ void to_half(const float* __restrict__ in, __half* __restrict__ out, int n4) {
    int i = blockIdx.x * blockDim.x + threadIdx.x;
    if (i < n4) {
        float4 v = ((const float4*)in)[i];
        __half2* o = (__half2*)(out + i * 4);
        o[0] = __floats2half2_rn(v.x, v.y);
        o[1] = __floats2half2_rn(v.z, v.w);
    }
}

// in: [R, Ccols] fp32 row-major -> out: [Ccols, R] half row-major
__global__ void transpose_half(const float* __restrict__ in, __half* __restrict__ out,
                               int R, int Ccols) {
    __shared__ float t[32][33];
    int bx = blockIdx.x * 32;
    int by = blockIdx.y * 32;
    int x = threadIdx.x, y = threadIdx.y;
#pragma unroll
    for (int j = 0; j < 32; j += 8)
        t[y + j][x] = in[(size_t)(by + y + j) * Ccols + bx + x];
    __syncthreads();
#pragma unroll
    for (int j = 0; j < 32; j += 8)
        out[(size_t)(bx + y + j) * R + by + x] = __float2half_rn(t[x][y + j]);
}

// ---------------------------------------------------------------------------
// FP16 GEMM (R6 config): C[M, N] = A[M,1024] @ Bt[N,1024]^T + bias (fp32 acc)
// BM=128 BN=128 BK=64 halves, 256 threads (8 warps 2x4), warp tile 64x32.
// cp.async 3-stage, 1 sync/iter, ldmatrix both operands.
// MODE 0: convert to half + scatter q/k (BHTD) and vt (BHDT).
// MODE 1: fp32 row-major store + bias.
// ---------------------------------------------------------------------------
#define GKT 16                    // k-tiles (K=1024 / 64)
#define STAGE_B 16384             // 128 rows x 128B
#define GEMM_SMEM (6 * STAGE_B)   // 3 stages x (A+B) = 98304

template <int MODE>
__global__ __launch_bounds__(256, 2) void gemm_f16(
    const __half* __restrict__ Ag, const __half* __restrict__ Bg,
    const float* __restrict__ bias, float* __restrict__ Cout, int N)
{
    extern __shared__ char smem[];
    const uint32_t sA = smem_u32(smem);
    const uint32_t sB = sA + 3 * STAGE_B;

    const int tid  = threadIdx.x;
    const int lane = tid & 31;
    const int wid  = tid >> 5;
    const int wr   = (wid >> 2) * 64;
    const int wc   = (wid & 3) * 32;
    const int m0   = blockIdx.y * 128;
    const int n0   = blockIdx.x * 128;

    const int lr = tid >> 3;      // + i*32
    const int lg = tid & 7;       // 16B group (8 halves)

    auto issue = [&](int kt) {
        const int s = kt % 3;
#pragma unroll
        for (int i = 0; i < 4; i++) {
            int r = lr + i * 32;
            uint32_t off = r * 128 + ((lg ^ (r & 7)) << 4);
            cp_async16(sA + s * STAGE_B + off,
                       Ag + (size_t)(m0 + r) * 1024 + kt * 64 + lg * 8);
            cp_async16(sB + s * STAGE_B + off,
                       Bg + (size_t)(n0 + r) * 1024 + kt * 64 + lg * 8);
        }
        cp_commit();
    };

    const int arow  = wr + (lane & 7) + 8 * ((lane >> 3) & 1);
    const int kha   = lane >> 4;
    const int brow0 = wc + (lane & 7) + 8 * (lane >> 4);
    const int khb   = (lane >> 3) & 1;

    float acc[4][4][4];
#pragma unroll
    for (int mi = 0; mi < 4; mi++)
#pragma unroll
        for (int ni = 0; ni < 4; ni++)
#pragma unroll
            for (int r = 0; r < 4; r++) acc[mi][ni][r] = 0.0f;

    issue(0);
    issue(1);

    for (int kt = 0; kt < GKT; kt++) {
        if (kt + 1 < GKT) cp_wait<1>(); else cp_wait<0>();
        __syncthreads();
        if (kt + 2 < GKT) issue(kt + 2);

        const int s = kt % 3;
        const uint32_t aS = sA + s * STAGE_B;
        const uint32_t bS = sB + s * STAGE_B;

#pragma unroll
        for (int kk = 0; kk < 4; kk++) {
            uint32_t af[4][4];
#pragma unroll
            for (int mi = 0; mi < 4; mi++) {
                int r = arow + mi * 16;
                uint32_t addr = aS + r * 128 +
                                ((((kk << 1) | kha) ^ (r & 7)) << 4);
                ldsm_x4(af[mi], addr);
            }
            uint32_t bf[4][2];
#pragma unroll
            for (int p = 0; p < 2; p++) {
                int r = brow0 + p * 16;
                uint32_t addr = bS + r * 128 +
                                ((((kk << 1) | khb) ^ (r & 7)) << 4);
                uint32_t d[4];
                ldsm_x4(d, addr);
                bf[2 * p][0] = d[0]; bf[2 * p][1] = d[1];
                bf[2 * p + 1][0] = d[2]; bf[2 * p + 1][1] = d[3];
            }
#pragma unroll
            for (int mi = 0; mi < 4; mi++)
#pragma unroll
                for (int ni = 0; ni < 4; ni++)
                    mma_f16(acc[mi][ni], af[mi], bf[ni], acc[mi][ni]);
        }
    }

    // Epilogue
    const int g  = lane >> 2;
    const int tg = lane & 3;
#pragma unroll
    for (int mi = 0; mi < 4; mi++) {
#pragma unroll
        for (int ni = 0; ni < 4; ni++) {
#pragma unroll
            for (int r = 0; r < 4; r++) {
                int row = m0 + wr + mi * 16 + g + ((r >> 1) ? 8 : 0);
                int col = n0 + wc + ni * 8 + tg * 2 + (r & 1);
                float v = acc[mi][ni][r] + __ldg(&bias[col]);
                if (MODE == 0) {
                    __half hv = __float2half_rn(v);
                    int b = row >> 11;
                    int t = row & (T_ - 1);
                    int which = col >> 10;
                    int rr = col & (C_ - 1);
                    int h = rr >> 6;
                    int d = rr & 63;
                    size_t bhh = (size_t)(b * H_ + h);
                    if (which == 2) {
                        g_vt16[(bhh * D_ + d) * T_ + t] = hv;
                    } else {
                        __half* dst = (which == 0) ? g_q16 : g_k16;
                        dst[(bhh * T_ + t) * D_ + d] = hv;
                    }
                } else {
                    Cout[(size_t)row * N + col] = v;
                }
            }
        }
    }
}

// ---------------------------------------------------------------------------
// Flash attention (causal), fp16 mma, BQ=128 BKV=64, 256 threads (8 warps),
// each warp owns a 16-row q slab. FA2: P kept in registers (S-accum fragment
// == PV A-fragment layout), no P smem, no P ldsm. K/Vt 3-stage cp.async ring,
// single sync per iteration. Softmax fp32 base-2. LPT (qi reversed).
// smem 64KB -> 2 CTAs/SM.
// ---------------------------------------------------------------------------
#define AQB 16384                        // Q: 128 rows x 128B
#define AKV 8192                         // K/Vt tile: 64 rows x 128B
#define AQ_OFF 0
#define AK_OFF AQB                       // + s*AKV   (3 stages)
#define AV_OFF (AQB + 3 * AKV)           // + s*AKV   (3 stages)
#define ATTN_SMEM (AQB + 6 * AKV)        // 65536 bytes

__global__ __launch_bounds__(256, 2) void attn_kernel()
{
    extern __shared__ char smc[];
    const uint32_t sQ = smem_u32(smc);

    const int bh  = blockIdx.x;
    const int b   = bh >> 4;
    const int h   = bh & 15;
    const int qi  = (T_ / 128 - 1) - blockIdx.y;   // longest-first
    const int tid = threadIdx.x;
    const int lane = tid & 31;
    const int wid  = tid >> 5;
    const int g    = lane >> 2;
    const int tg   = lane & 3;

    const __half* Qg  = g_q16  + ((size_t)bh * T_ + qi * 128) * D_;
    const __half* Kg  = g_k16  + (size_t)bh * T_ * D_;
    const __half* Vtg = g_vt16 + (size_t)bh * D_ * T_;

    // Q tile (128x64 halves) -> swizzled smem
#pragma unroll
    for (int it = 0; it < 4; it++) {
        int i = tid + it * 256;
        int r = i >> 3, gg = i & 7;
        uint4 v = *(const uint4*)&Qg[r * 64 + gg * 8];
        *(uint4*)(smc + r * 128 + ((gg ^ (r & 7)) << 4)) = v;
    }

    auto issue = [&](int j) {
        const int s = j % 3;
#pragma unroll
        for (int it = 0; it < 2; it++) {
            int i = tid + it * 256;
            int r = i >> 3, gg = i & 7;
            uint32_t sw = r * 128 + ((gg ^ (r & 7)) << 4);
            cp_async16(sQ + AK_OFF + s * AKV + sw,
                       Kg + ((size_t)j * 64 + r) * 64 + gg * 8);
            cp_async16(sQ + AV_OFF + s * AKV + sw,
                       Vtg + (size_t)r * T_ + j * 64 + gg * 8);
        }
        cp_commit();
    };

    const int jmax = 2 * qi + 1;
    issue(0);
    issue(1);

    // fragment lane constants
    const int qrow = wid * 16 + (lane & 7) + 8 * ((lane >> 3) & 1);
    const int khq  = lane >> 4;
    const int qxk  = qrow & 7;
    const uint32_t qbase = sQ + AQ_OFF + qrow * 128;
    const int brow = (lane & 7) + 8 * (lane >> 4);    // + p*16
    const int khb  = (lane >> 3) & 1;

    float O[8][4];
#pragma unroll
    for (int ni = 0; ni < 8; ni++)
#pragma unroll
        for (int r = 0; r < 4; r++) O[ni][r] = 0.0f;
    float mrow0 = -1e30f, mrow1 = -1e30f;
    float lrow0 = 0.0f,   lrow1 = 0.0f;

    const int rloc = wid * 16 + g;
    const float scale = 0.125f * 1.4426950408889634f;   // 1/sqrt(D) * log2(e)

    for (int j = 0; j <= jmax; j++) {
        const int s = j % 3;
        if (j < jmax) cp_wait<1>(); else cp_wait<0>();
        __syncthreads();
        // 3-stage ring: stage (j+2)%3 == stage (j-1)%3, fully consumed before
        // this iteration's sync -> safe to overwrite now, no bottom sync.
        if (j + 2 <= jmax) issue(j + 2);

        const uint32_t kS = sQ + AK_OFF + s * AKV;
        const uint32_t vS = sQ + AV_OFF + s * AKV;

        // S = Q K^T  (fp32 accum)
        float sfr[8][4];
#pragma unroll
        for (int ni = 0; ni < 8; ni++)
#pragma unroll
            for (int r = 0; r < 4; r++) sfr[ni][r] = 0.0f;

#pragma unroll
        for (int kk = 0; kk < 4; kk++) {
            uint32_t af[4];
            ldsm_x4(af, qbase + ((((kk << 1) | khq) ^ qxk) << 4));
            uint32_t bf[8][2];
#pragma unroll
            for (int p = 0; p < 4; p++) {
                int r = brow + p * 16;
                uint32_t d[4];
                ldsm_x4(d, kS + r * 128 + ((((kk << 1) | khb) ^ (r & 7)) << 4));
                bf[2 * p][0] = d[0]; bf[2 * p][1] = d[1];
                bf[2 * p + 1][0] = d[2]; bf[2 * p + 1][1] = d[3];
            }
#pragma unroll
            for (int ni = 0; ni < 8; ni++)
                mma_f16(sfr[ni], af, bf[ni], sfr[ni]);
        }

        // Scale (base-2) + causal mask (last two kv tiles straddle diagonal)
        const bool diag = (j >= 2 * qi);
        const int rowg0 = qi * 128 + rloc;
        const int rowg1 = rowg0 + 8;
#pragma unroll
        for (int ni = 0; ni < 8; ni++) {
#pragma unroll
            for (int r = 0; r < 4; r++) {
                float sv = sfr[ni][r] * scale;
                if (diag) {
                    int colg = j * 64 + ni * 8 + tg * 2 + (r & 1);
                    int rowg = (r >> 1) ? rowg1 : rowg0;
                    if (colg > rowg) sv = -1e30f;
                }
                sfr[ni][r] = sv;
            }
        }

        // Online softmax (base-2; two rows per thread)
        float mx0 = -1e30f, mx1 = -1e30f;
#pragma unroll
        for (int ni = 0; ni < 8; ni++) {
            mx0 = fmaxf(mx0, fmaxf(sfr[ni][0], sfr[ni][1]));
            mx1 = fmaxf(mx1, fmaxf(sfr[ni][2], sfr[ni][3]));
        }
        mx0 = fmaxf(mx0, __shfl_xor_sync(0xffffffffu, mx0, 1));
        mx0 = fmaxf(mx0, __shfl_xor_sync(0xffffffffu, mx0, 2));
        mx1 = fmaxf(mx1, __shfl_xor_sync(0xffffffffu, mx1, 1));
        mx1 = fmaxf(mx1, __shfl_xor_sync(0xffffffffu, mx1, 2));

        float mn0 = fmaxf(mrow0, mx0);
        float mn1 = fmaxf(mrow1, mx1);
        float a0 = ex2f(mrow0 - mn0);
        float a1 = ex2f(mrow1 - mn1);

        float rs0 = 0.0f, rs1 = 0.0f;
#pragma unroll
        for (int ni = 0; ni < 8; ni++) {
            float p0 = ex2f(sfr[ni][0] - mn0); sfr[ni][0] = p0; rs0 += p0;
            float p1 = ex2f(sfr[ni][1] - mn0); sfr[ni][1] = p1; rs0 += p1;
            float p2 = ex2f(sfr[ni][2] - mn1); sfr[ni][2] = p2; rs1 += p2;
            float p3 = ex2f(sfr[ni][3] - mn1); sfr[ni][3] = p3; rs1 += p3;
        }
        rs0 += __shfl_xor_sync(0xffffffffu, rs0, 1);
        rs0 += __shfl_xor_sync(0xffffffffu, rs0, 2);
        rs1 += __shfl_xor_sync(0xffffffffu, rs1, 1);
        rs1 += __shfl_xor_sync(0xffffffffu, rs1, 2);

        lrow0 = lrow0 * a0 + rs0;
        lrow1 = lrow1 * a1 + rs1;
        mrow0 = mn0;
        mrow1 = mn1;

#pragma unroll
        for (int ni = 0; ni < 8; ni++) {
            O[ni][0] *= a0; O[ni][1] *= a0;
            O[ni][2] *= a1; O[ni][3] *= a1;
        }

        // O += P @ V : FA2 repack — S accumulator fragment IS the PV
        // A-operand fragment (rows g/g+8, k-cols 2tg(+1) per 8-block).
#pragma unroll
        for (int kk = 0; kk < 4; kk++) {
            uint32_t af[4];
            af[0] = packh2(sfr[2 * kk    ][0], sfr[2 * kk    ][1]);
            af[1] = packh2(sfr[2 * kk    ][2], sfr[2 * kk    ][3]);
            af[2] = packh2(sfr[2 * kk + 1][0], sfr[2 * kk + 1][1]);
            af[3] = packh2(sfr[2 * kk + 1][2], sfr[2 * kk + 1][3]);
            uint32_t bf[8][2];
#pragma unroll
            for (int p = 0; p < 4; p++) {
                int r = brow + p * 16;
                uint32_t d[4];
                ldsm_x4(d, vS + r * 128 + ((((kk << 1) | khb) ^ (r & 7)) << 4));
                bf[2 * p][0] = d[0]; bf[2 * p][1] = d[1];
                bf[2 * p + 1][0] = d[2]; bf[2 * p + 1][1] = d[3];
            }
#pragma unroll
            for (int ni = 0; ni < 8; ni++)
                mma_f16(O[ni], af, bf[ni], O[ni]);
        }
    }

    // Epilogue: O /= l, convert to half, write [B,T,H,D]
    float il0 = 1.0f / lrow0;
    float il1 = 1.0f / lrow1;
    int t0 = qi * 128 + rloc;
#pragma unroll
    for (int ni = 0; ni < 8; ni++) {
        int d = ni * 8 + tg * 2;
        size_t base0 = ((size_t)(b * T_ + t0    ) * H_ + h) * D_ + d;
        size_t base1 = ((size_t)(b * T_ + t0 + 8) * H_ + h) * D_ + d;
        *(__half2*)&g_y16[base0] = __floats2half2_rn(O[ni][0] * il0, O[ni][1] * il0);
        *(__half2*)&g_y16[base1] = __floats2half2_rn(O[ni][2] * il1, O[ni][3] * il1);
    }
}

// ---------------------------------------------------------------------------
// Launch
// ---------------------------------------------------------------------------
extern "C" void kernel_launch(void* const* d_in, const int* in_sizes, int n_in,
                              void* d_out, int out_size)
{
    const float* x     = (const float*)d_in[0];
    const float* Wqkv  = (const float*)d_in[1];
    const float* bqkv  = (const float*)d_in[2];
    const float* Wout  = (const float*)d_in[3];
    const float* bout  = (const float*)d_in[4];
    float* out = (float*)d_out;

    __half *x16 = nullptr, *wqkvT = nullptr, *woutT = nullptr, *y16 = nullptr;
    cudaGetSymbolAddress((void**)&x16, g_x16);
    cudaGetSymbolAddress((void**)&wqkvT, g_wqkvT16);
    cudaGetSymbolAddress((void**)&woutT, g_woutT16);
    cudaGetSymbolAddress((void**)&y16, g_y16);

    cudaFuncSetAttribute(gemm_f16<0>,
                         cudaFuncAttributeMaxDynamicSharedMemorySize, GEMM_SMEM);
    cudaFuncSetAttribute(gemm_f16<1>,
                         cudaFuncAttributeMaxDynamicSharedMemorySize, GEMM_SMEM);
    cudaFuncSetAttribute(attn_kernel,
                         cudaFuncAttributeMaxDynamicSharedMemorySize, ATTN_SMEM);

    // 0) prep: x -> half; W^T -> half
    to_half<<<(B_ * T_ * C_ / 4 + 255) / 256, 256>>>(x, x16, B_ * T_ * C_ / 4);
    transpose_half<<<dim3(3 * C_ / 32, C_ / 32), dim3(32, 8)>>>(Wqkv, wqkvT, C_, 3 * C_);
    transpose_half<<<dim3(C_ / 32, C_ / 32), dim3(32, 8)>>>(Wout, woutT, C_, C_);

    // 1) QKV projection -> q/k (BHTD) + vt (BHDT), half
    gemm_f16<0><<<dim3(3 * C_ / 128, B_ * T_ / 128), 256, GEMM_SMEM>>>(
        x16, wqkvT, bqkv, nullptr, 3 * C_);

    // 2) Causal flash attention -> g_y16
    attn_kernel<<<dim3(BH_, T_ / 128), 256, ATTN_SMEM>>>();

    // 3) Output projection -> out (fp32)
    gemm_f16<1><<<dim3(C_ / 128, B_ * T_ / 128), 256, GEMM_SMEM>>>(
        y16, woutT, bout, out, C_);
}

// round 11
// speedup vs baseline: 3.5000x; 1.0135x over previous
#include <cuda_runtime.h>
#include <cuda_fp16.h>
#include <cstdint>
#include <math.h>

// Problem constants
#define B_ 4
#define T_ 2048
#define C_ 1024
#define H_ 16
#define D_ 64
#define BH_ (B_ * H_)

// Scratch (device globals -- no allocation allowed)
__device__ __half g_q16[BH_ * T_ * D_];     // [B,H,T,D]
__device__ __half g_k16[BH_ * T_ * D_];     // [B,H,T,D]
__device__ __half g_vt16[BH_ * D_ * T_];    // [B,H,D,T]  (V transposed)
__device__ __half g_y16[B_ * T_ * C_];      // [B,T,C]
__device__ __half g_x16[B_ * T_ * C_];      // x -> half
__device__ __half g_wqkvT16[3 * C_ * C_];   // [3C, C] = W_qkv^T
__device__ __half g_woutT16[C_ * C_];       // [C, C]  = W_out^T

// Flag counters for the in-kernel pipeline (zeroed by prep each call)
__device__ int g_cnt0[64];   // per qkv row-tile: col-tiles done (24 = ready)
__device__ int g_cnt1[64];   // per (b,qi) group: heads done (16 = ready)

// ---------------------------------------------------------------------------
// Helpers
// ---------------------------------------------------------------------------
__device__ __forceinline__ uint32_t smem_u32(const void* p) {
    return (uint32_t)__cvta_generic_to_shared(p);
}

__device__ __forceinline__ float ex2f(float x) {
    float y;
    asm("ex2.approx.f32 %0, %1;" : "=f"(y) : "f"(x));
    return y;
}

__device__ __forceinline__ uint32_t packh2(float a, float b) {
    __half2 h = __floats2half2_rn(a, b);
    return *(uint32_t*)&h;
}

__device__ __forceinline__ void mma_f16(float d[4], const uint32_t a[4],
                                        const uint32_t b[2], const float c[4]) {
    asm volatile(
        "mma.sync.aligned.m16n8k16.row.col.f32.f16.f16.f32 "
        "{%0,%1,%2,%3},{%4,%5,%6,%7},{%8,%9},{%10,%11,%12,%13};"
        : "=f"(d[0]), "=f"(d[1]), "=f"(d[2]), "=f"(d[3])
        : "r"(a[0]), "r"(a[1]), "r"(a[2]), "r"(a[3]),
          "r"(b[0]), "r"(b[1]),
          "f"(c[0]), "f"(c[1]), "f"(c[2]), "f"(c[3]));
}

__device__ __forceinline__ void ldsm_x4(uint32_t d[4], uint32_t saddr) {
    asm volatile(
        "ldmatrix.sync.aligned.m8n8.x4.shared.b16 {%0,%1,%2,%3}, [%4];"
        : "=r"(d[0]), "=r"(d[1]), "=r"(d[2]), "=r"(d[3]) : "r"(saddr));
}

__device__ __forceinline__ void cp_async16(uint32_t dst, const void* src) {
    asm volatile("cp.async.cg.shared.global [%0], [%1], 16;"
                 :: "r"(dst), "l"(src) : "memory");
}
__device__ __forceinline__ void cp_commit() {
    asm volatile("cp.async.commit_group;" ::: "memory");
}
template <int N>
__device__ __forceinline__ void cp_wait() {
    asm volatile("cp.async.wait_group %0;" :: "n"(N) : "memory");
}

// ---------------------------------------------------------------------------
// Prep kernels: fp32 -> fp16 copies / transposes (+ flag zeroing)
// ---------------------------------------------------------------------------
__global__ void to_half(const float* __restrict__ in, __half* __restrict__ out, int n4) {
    if (blockIdx.x == 0 && threadIdx.x < 64) {
        g_cnt0[threadIdx.x] = 0;
        g_cnt1[threadIdx.x] = 0;
    }
    int i = blockIdx.x * blockDim.x + threadIdx.x;
    if (i < n4) {
        float4 v = ((const float4*)in)[i];
        __half2* o = (__half2*)(out + i * 4);
        o[0] = __floats2half2_rn(v.x, v.y);
        o[1] = __floats2half2_rn(v.z, v.w);
    }
}

// in: [R, Ccols] fp32 row-major -> out: [Ccols, R] half row-major
__global__ void transpose_half(const float* __restrict__ in, __half* __restrict__ out,
                               int R, int Ccols) {
    __shared__ float t[32][33];
    int bx = blockIdx.x * 32;
    int by = blockIdx.y * 32;
    int x = threadIdx.x, y = threadIdx.y;
#pragma unroll
    for (int j = 0; j < 32; j += 8)
        t[y + j][x] = in[(size_t)(by + y + j) * Ccols + bx + x];
    __syncthreads();
#pragma unroll
    for (int j = 0; j < 32; j += 8)
        out[(size_t)(bx + y + j) * R + by + x] = __float2half_rn(t[x][y + j]);
}

// ---------------------------------------------------------------------------
// FP16 GEMM body: C[m0..][N] tile = A @ Bt^T + bias (fp32 acc)
// BM=128 BN=128 BK=64 halves, 256 threads (8 warps 2x4), warp tile 64x32.
// cp.async 3-stage, 1 sync/iter, ldmatrix both operands.
// MODE 0: convert to half + scatter q/k (BHTD) and vt (BHDT).
// MODE 1: fp32 row-major store + bias.
// ---------------------------------------------------------------------------
#define GKT 16                    // k-tiles (K=1024 / 64)
#define STAGE_B 16384             // 128 rows x 128B
#define GEMM_SMEM (6 * STAGE_B)   // 3 stages x (A+B) = 98304

template <int MODE>
__device__ __forceinline__ void gemm_body(
    char* smem, const __half* __restrict__ Ag, const __half* __restrict__ Bg,
    const float* __restrict__ bias, float* __restrict__ Cout, int N,
    int m0, int n0)
{
    const uint32_t sA = smem_u32(smem);
    const uint32_t sB = sA + 3 * STAGE_B;

    const int tid  = threadIdx.x;
    const int lane = tid & 31;
    const int wid  = tid >> 5;
    const int wr   = (wid >> 2) * 64;
    const int wc   = (wid & 3) * 32;

    const int lr = tid >> 3;      // + i*32
    const int lg = tid & 7;       // 16B group (8 halves)

    auto issue = [&](int kt) {
        const int s = kt % 3;
#pragma unroll
        for (int i = 0; i < 4; i++) {
            int r = lr + i * 32;
            uint32_t off = r * 128 + ((lg ^ (r & 7)) << 4);
            cp_async16(sA + s * STAGE_B + off,
                       Ag + (size_t)(m0 + r) * 1024 + kt * 64 + lg * 8);
            cp_async16(sB + s * STAGE_B + off,
                       Bg + (size_t)(n0 + r) * 1024 + kt * 64 + lg * 8);
        }
        cp_commit();
    };

    const int arow  = wr + (lane & 7) + 8 * ((lane >> 3) & 1);
    const int kha   = lane >> 4;
    const int brow0 = wc + (lane & 7) + 8 * (lane >> 4);
    const int khb   = (lane >> 3) & 1;

    float acc[4][4][4];
#pragma unroll
    for (int mi = 0; mi < 4; mi++)
#pragma unroll
        for (int ni = 0; ni < 4; ni++)
#pragma unroll
            for (int r = 0; r < 4; r++) acc[mi][ni][r] = 0.0f;

    issue(0);
    issue(1);

    for (int kt = 0; kt < GKT; kt++) {
        if (kt + 1 < GKT) cp_wait<1>(); else cp_wait<0>();
        __syncthreads();
        if (kt + 2 < GKT) issue(kt + 2);

        const int s = kt % 3;
        const uint32_t aS = sA + s * STAGE_B;
        const uint32_t bS = sB + s * STAGE_B;

#pragma unroll
        for (int kk = 0; kk < 4; kk++) {
            uint32_t af[4][4];
#pragma unroll
            for (int mi = 0; mi < 4; mi++) {
                int r = arow + mi * 16;
                uint32_t addr = aS + r * 128 +
                                ((((kk << 1) | kha) ^ (r & 7)) << 4);
                ldsm_x4(af[mi], addr);
            }
            uint32_t bf[4][2];
#pragma unroll
            for (int p = 0; p < 2; p++) {
                int r = brow0 + p * 16;
                uint32_t addr = bS + r * 128 +
                                ((((kk << 1) | khb) ^ (r & 7)) << 4);
                uint32_t d[4];
                ldsm_x4(d, addr);
                bf[2 * p][0] = d[0]; bf[2 * p][1] = d[1];
                bf[2 * p + 1][0] = d[2]; bf[2 * p + 1][1] = d[3];
            }
#pragma unroll
            for (int mi = 0; mi < 4; mi++)
#pragma unroll
                for (int ni = 0; ni < 4; ni++)
                    mma_f16(acc[mi][ni], af[mi], bf[ni], acc[mi][ni]);
        }
    }

    // Epilogue
    const int g  = lane >> 2;
    const int tg = lane & 3;
#pragma unroll
    for (int mi = 0; mi < 4; mi++) {
#pragma unroll
        for (int ni = 0; ni < 4; ni++) {
#pragma unroll
            for (int r = 0; r < 4; r++) {
                int row = m0 + wr + mi * 16 + g + ((r >> 1) ? 8 : 0);
                int col = n0 + wc + ni * 8 + tg * 2 + (r & 1);
                float v = acc[mi][ni][r] + __ldg(&bias[col]);
                if (MODE == 0) {
                    __half hv = __float2half_rn(v);
                    int b = row >> 11;
                    int t = row & (T_ - 1);
                    int which = col >> 10;
                    int rr = col & (C_ - 1);
                    int h = rr >> 6;
                    int d = rr & 63;
                    size_t bhh = (size_t)(b * H_ + h);
                    if (which == 2) {
                        g_vt16[(bhh * D_ + d) * T_ + t] = hv;
                    } else {
                        __half* dst = (which == 0) ? g_q16 : g_k16;
                        dst[(bhh * T_ + t) * D_ + d] = hv;
                    }
                } else {
                    Cout[(size_t)row * N + col] = v;
                }
            }
        }
    }
}

// ---------------------------------------------------------------------------
// Flash attention body (causal), fp16 mma, BQ=128 BKV=64, 256 threads
// (8 warps, one 16-row q slab each). FA2: P in registers. K/Vt 3-stage
// cp.async ring, 1 sync/iter. Softmax fp32 base-2. Uses 64KB of smem.
// ---------------------------------------------------------------------------
#define AQB 16384                        // Q: 128 rows x 128B
#define AKV 8192                         // K/Vt tile: 64 rows x 128B
#define AQ_OFF 0
#define AK_OFF AQB                       // + s*AKV   (3 stages)
#define AV_OFF (AQB + 3 * AKV)           // + s*AKV   (3 stages)

__device__ __forceinline__ void attn_body(char* smc, int b, int h, int qi)
{
    const uint32_t sQ = smem_u32(smc);
    const int bh  = b * H_ + h;
    const int tid = threadIdx.x;
    const int lane = tid & 31;
    const int wid  = tid >> 5;
    const int g    = lane >> 2;
    const int tg   = lane & 3;

    const __half* Qg  = g_q16  + ((size_t)bh * T_ + qi * 128) * D_;
    const __half* Kg  = g_k16  + (size_t)bh * T_ * D_;
    const __half* Vtg = g_vt16 + (size_t)bh * D_ * T_;

    // Q tile (128x64 halves) -> swizzled smem
#pragma unroll
    for (int it = 0; it < 4; it++) {
        int i = tid + it * 256;
        int r = i >> 3, gg = i & 7;
        uint4 v = *(const uint4*)&Qg[r * 64 + gg * 8];
        *(uint4*)(smc + r * 128 + ((gg ^ (r & 7)) << 4)) = v;
    }

    auto issue = [&](int j) {
        const int s = j % 3;
#pragma unroll
        for (int it = 0; it < 2; it++) {
            int i = tid + it * 256;
            int r = i >> 3, gg = i & 7;
            uint32_t sw = r * 128 + ((gg ^ (r & 7)) << 4);
            cp_async16(sQ + AK_OFF + s * AKV + sw,
                       Kg + ((size_t)j * 64 + r) * 64 + gg * 8);
            cp_async16(sQ + AV_OFF + s * AKV + sw,
                       Vtg + (size_t)r * T_ + j * 64 + gg * 8);
        }
        cp_commit();
    };

    const int jmax = 2 * qi + 1;
    issue(0);
    issue(1);

    // fragment lane constants
    const int qrow = wid * 16 + (lane & 7) + 8 * ((lane >> 3) & 1);
    const int khq  = lane >> 4;
    const int qxk  = qrow & 7;
    const uint32_t qbase = sQ + AQ_OFF + qrow * 128;
    const int brow = (lane & 7) + 8 * (lane >> 4);    // + p*16
    const int khb  = (lane >> 3) & 1;

    float O[8][4];
#pragma unroll
    for (int ni = 0; ni < 8; ni++)
#pragma unroll
        for (int r = 0; r < 4; r++) O[ni][r] = 0.0f;
    float mrow0 = -1e30f, mrow1 = -1e30f;
    float lrow0 = 0.0f,   lrow1 = 0.0f;

    const int rloc = wid * 16 + g;
    const float scale = 0.125f * 1.4426950408889634f;   // 1/sqrt(D) * log2(e)

    for (int j = 0; j <= jmax; j++) {
        const int s = j % 3;
        if (j < jmax) cp_wait<1>(); else cp_wait<0>();
        __syncthreads();
        if (j + 2 <= jmax) issue(j + 2);

        const uint32_t kS = sQ + AK_OFF + s * AKV;
        const uint32_t vS = sQ + AV_OFF + s * AKV;

        // S = Q K^T  (fp32 accum)
        float sfr[8][4];
#pragma unroll
        for (int ni = 0; ni < 8; ni++)
#pragma unroll
            for (int r = 0; r < 4; r++) sfr[ni][r] = 0.0f;

#pragma unroll
        for (int kk = 0; kk < 4; kk++) {
            uint32_t af[4];
            ldsm_x4(af, qbase + ((((kk << 1) | khq) ^ qxk) << 4));
            uint32_t bf[8][2];
#pragma unroll
            for (int p = 0; p < 4; p++) {
                int r = brow + p * 16;
                uint32_t d[4];
                ldsm_x4(d, kS + r * 128 + ((((kk << 1) | khb) ^ (r & 7)) << 4));
                bf[2 * p][0] = d[0]; bf[2 * p][1] = d[1];
                bf[2 * p + 1][0] = d[2]; bf[2 * p + 1][1] = d[3];
            }
#pragma unroll
            for (int ni = 0; ni < 8; ni++)
                mma_f16(sfr[ni], af, bf[ni], sfr[ni]);
        }

        // Scale (base-2) + causal mask (last two kv tiles straddle diagonal)
        const bool diag = (j >= 2 * qi);
        const int rowg0 = qi * 128 + rloc;
        const int rowg1 = rowg0 + 8;
#pragma unroll
        for (int ni = 0; ni < 8; ni++) {
#pragma unroll
            for (int r = 0; r < 4; r++) {
                float sv = sfr[ni][r] * scale;
                if (diag) {
                    int colg = j * 64 + ni * 8 + tg * 2 + (r & 1);
                    int rowg = (r >> 1) ? rowg1 : rowg0;
                    if (colg > rowg) sv = -1e30f;
                }
                sfr[ni][r] = sv;
            }
        }

        // Online softmax (base-2; two rows per thread)
        float mx0 = -1e30f, mx1 = -1e30f;
#pragma unroll
        for (int ni = 0; ni < 8; ni++) {
            mx0 = fmaxf(mx0, fmaxf(sfr[ni][0], sfr[ni][1]));
            mx1 = fmaxf(mx1, fmaxf(sfr[ni][2], sfr[ni][3]));
        }
        mx0 = fmaxf(mx0, __shfl_xor_sync(0xffffffffu, mx0, 1));
        mx0 = fmaxf(mx0, __shfl_xor_sync(0xffffffffu, mx0, 2));
        mx1 = fmaxf(mx1, __shfl_xor_sync(0xffffffffu, mx1, 1));
        mx1 = fmaxf(mx1, __shfl_xor_sync(0xffffffffu, mx1, 2));

        float mn0 = fmaxf(mrow0, mx0);
        float mn1 = fmaxf(mrow1, mx1);
        float a0 = ex2f(mrow0 - mn0);
        float a1 = ex2f(mrow1 - mn1);

        float rs0 = 0.0f, rs1 = 0.0f;
#pragma unroll
        for (int ni = 0; ni < 8; ni++) {
            float p0 = ex2f(sfr[ni][0] - mn0); sfr[ni][0] = p0; rs0 += p0;
            float p1 = ex2f(sfr[ni][1] - mn0); sfr[ni][1] = p1; rs0 += p1;
            float p2 = ex2f(sfr[ni][2] - mn1); sfr[ni][2] = p2; rs1 += p2;
            float p3 = ex2f(sfr[ni][3] - mn1); sfr[ni][3] = p3; rs1 += p3;
        }
        rs0 += __shfl_xor_sync(0xffffffffu, rs0, 1);
        rs0 += __shfl_xor_sync(0xffffffffu, rs0, 2);
        rs1 += __shfl_xor_sync(0xffffffffu, rs1, 1);
        rs1 += __shfl_xor_sync(0xffffffffu, rs1, 2);

        lrow0 = lrow0 * a0 + rs0;
        lrow1 = lrow1 * a1 + rs1;
        mrow0 = mn0;
        mrow1 = mn1;

#pragma unroll
        for (int ni = 0; ni < 8; ni++) {
            O[ni][0] *= a0; O[ni][1] *= a0;
            O[ni][2] *= a1; O[ni][3] *= a1;
        }

        // O += P @ V : FA2 repack — S accumulator fragment IS the PV
        // A-operand fragment.
#pragma unroll
        for (int kk = 0; kk < 4; kk++) {
            uint32_t af[4];
            af[0] = packh2(sfr[2 * kk    ][0], sfr[2 * kk    ][1]);
            af[1] = packh2(sfr[2 * kk    ][2], sfr[2 * kk    ][3]);
            af[2] = packh2(sfr[2 * kk + 1][0], sfr[2 * kk + 1][1]);
            af[3] = packh2(sfr[2 * kk + 1][2], sfr[2 * kk + 1][3]);
            uint32_t bf[8][2];
#pragma unroll
            for (int p = 0; p < 4; p++) {
                int r = brow + p * 16;
                uint32_t d[4];
                ldsm_x4(d, vS + r * 128 + ((((kk << 1) | khb) ^ (r & 7)) << 4));
                bf[2 * p][0] = d[0]; bf[2 * p][1] = d[1];
                bf[2 * p + 1][0] = d[2]; bf[2 * p + 1][1] = d[3];
            }
#pragma unroll
            for (int ni = 0; ni < 8; ni++)
                mma_f16(O[ni], af, bf[ni], O[ni]);
        }
    }

    // Epilogue: O /= l, convert to half, write [B,T,H,D]
    float il0 = 1.0f / lrow0;
    float il1 = 1.0f / lrow1;
    int t0 = qi * 128 + rloc;
#pragma unroll
    for (int ni = 0; ni < 8; ni++) {
        int d = ni * 8 + tg * 2;
        size_t base0 = ((size_t)(b * T_ + t0    ) * H_ + h) * D_ + d;
        size_t base1 = ((size_t)(b * T_ + t0 + 8) * H_ + h) * D_ + d;
        *(__half2*)&g_y16[base0] = __floats2half2_rn(O[ni][0] * il0, O[ni][1] * il0);
        *(__half2*)&g_y16[base1] = __floats2half2_rn(O[ni][2] * il1, O[ni][3] * il1);
    }
}

// ---------------------------------------------------------------------------
// Mega kernel: grid-level pipeline via flag counters.
//   bids [0,1536):    qkv gemm tiles, row-groups ascending -> cnt0[rt]++
//   bids [1536,2560): attention (qi ascending), gated on cnt0 -> cnt1[grp]++
//   bids [2560,3072): out-proj tiles, gated on cnt1[grp]==16
// Consumers only wait on strictly-lower-bid producers.
// ---------------------------------------------------------------------------
#define MEGA_GRID 3072

__global__ __launch_bounds__(256, 2) void mega_kernel(
    const float* __restrict__ bqkv, const float* __restrict__ bout,
    float* __restrict__ out)
{
    extern __shared__ char smc[];
    const int bid = blockIdx.x;

    if (bid < 1536) {
        // ---- QKV GEMM tile ----
        int rt_pos = bid / 24;               // 0..63, ascending t-group
        int ct = bid - rt_pos * 24;          // 0..23
        int qi_r = rt_pos >> 2;              // t-tile within batch
        int b = rt_pos & 3;
        int rt = b * 16 + qi_r;              // row-tile id (= cnt0 index)
        gemm_body<0>(smc, g_x16, g_wqkvT16, bqkv, nullptr, 3 * C_,
                     rt * 128, ct * 128);
        __syncthreads();
        if (threadIdx.x == 0) {
            __threadfence();
            atomicAdd(&g_cnt0[rt], 1);
        }
    } else if (bid < 2560) {
        // ---- attention ----
        int idx = bid - 1536;
        int qi = idx >> 6;                   // ascending qi
        int bh = idx & 63;
        int b = bh >> 4;
        int h = bh & 15;
        if (threadIdx.x == 0) {
            for (int i = 0; i <= qi; i++)
                while (atomicAdd(&g_cnt0[b * 16 + i], 0) < 24) __nanosleep(128);
        }
        __syncthreads();
        attn_body(smc, b, h, qi);
        __syncthreads();
        if (threadIdx.x == 0) {
            __threadfence();
            atomicAdd(&g_cnt1[b * 16 + qi], 1);
        }
    } else {
        // ---- out-projection tile ----
        int idx = bid - 2560;
        int qi_g = idx >> 5;                 // ascending qi
        int b = (idx >> 3) & 3;
        int c = idx & 7;
        int grp = b * 16 + qi_g;
        if (threadIdx.x == 0) {
            while (atomicAdd(&g_cnt1[grp], 0) < 16) __nanosleep(128);
        }
        __syncthreads();
        gemm_body<1>(smc, g_y16, g_woutT16, bout, out, C_,
                     grp * 128, c * 128);
    }
}

// ---------------------------------------------------------------------------
// Launch
// ---------------------------------------------------------------------------
extern "C" void kernel_launch(void* const* d_in, const int* in_sizes, int n_in,
                              void* d_out, int out_size)
{
    const float* x     = (const float*)d_in[0];
    const float* Wqkv  = (const float*)d_in[1];
    const float* bqkv  = (const float*)d_in[2];
    const float* Wout  = (const float*)d_in[3];
    const float* bout  = (const float*)d_in[4];
    float* out = (float*)d_out;

    __half *x16 = nullptr, *wqkvT = nullptr, *woutT = nullptr;
    cudaGetSymbolAddress((void**)&x16, g_x16);
    cudaGetSymbolAddress((void**)&wqkvT, g_wqkvT16);
    cudaGetSymbolAddress((void**)&woutT, g_woutT16);

    cudaFuncSetAttribute(mega_kernel,
                         cudaFuncAttributeMaxDynamicSharedMemorySize, GEMM_SMEM);

    // 0) prep: x -> half (+ zero flags); W^T -> half
    to_half<<<(B_ * T_ * C_ / 4 + 255) / 256, 256>>>(x, x16, B_ * T_ * C_ / 4);
    transpose_half<<<dim3(3 * C_ / 32, C_ / 32), dim3(32, 8)>>>(Wqkv, wqkvT, C_, 3 * C_);
    transpose_half<<<dim3(C_ / 32, C_ / 32), dim3(32, 8)>>>(Wout, woutT, C_, C_);

    // 1) fused qkv-gemm -> attention -> out-proj pipeline, one launch
    mega_kernel<<<MEGA_GRID, 256, GEMM_SMEM>>>(bqkv, bout, out);
}